// round 2
// baseline (speedup 1.0000x reference)
#include <cuda_runtime.h>
#include <math.h>

#define NB 8
#define NO 128
#define NR 8
#define NH 48
#define NHW 2304
#define NX 64

// ---- output layout (concatenated flattened outputs, float32) ----
#define OFF_ATTN 0
#define OFF_Q    147456
#define OFF_PR   294912
#define OFF_A    294920
#define OFF_OFF  442376
#define OFF_TH   442384
#define OFF_Z    737296

// ---- device scratch (static, no runtime allocation) ----
__device__ float d_rot17[NR * NO * 17 * 17];
__device__ float d_rot33[NR * NO * 33 * 33];
__device__ float d_xout[NB * NO * NR * NHW];     // [b][c][r][hw]
__device__ float d_attn1[NB * NR * NHW];
__device__ float d_attn0[NB * 4 * NHW];
__device__ float d_z1[NB * 4 * NR * NHW];        // [b][l][r][hw]
__device__ float d_z0[NB * 4 * 4 * NHW];
__device__ float d_stats[NB * 4];                // m1, s1, m2, s2

__constant__ float c_offs[8] = {
    0.0f, 0.7853981633974483f, 1.5707963267948966f, 2.356194490192345f,
    3.141592653589793f, -2.356194490192345f, -1.5707963267948966f,
    -0.7853981633974483f};

#define LOG_SIGMA   1.1447298858494002f   // log(pi), f32
#define HALF_LOG2PI 0.9189385332046727f   // 0.5*log(2*pi), f32
#define PI_F        3.14159265358979323846f

// ============================================================
// K1: rotate kernels (bilinear grid_sample semantics, zero pad)
// ============================================================
template <int K>
__global__ void rotate_kern(const float* __restrict__ w) {
    constexpr int KK = K * K;
    float* out = (K == 17) ? d_rot17 : d_rot33;
    int idx = blockIdx.x * blockDim.x + threadIdx.x;
    if (idx >= NR * NO * KK) return;
    int j = idx % K;
    int t = idx / K;
    int i = t % K; t /= K;
    int o = t % NO;
    int r = t / NO;

    float theta = 0.7853981633974483f * (float)r;  // (2*pi/8)*r in f32
    float c = cosf(theta), s = sinf(theta);
    float gy = (2.0f * (float)i + 1.0f) / (float)K - 1.0f;
    float gx = (2.0f * (float)j + 1.0f) / (float)K - 1.0f;
    float sx = c * gx - s * gy;
    float sy = s * gx + c * gy;
    float fx = ((sx + 1.0f) * (float)K - 1.0f) * 0.5f;
    float fy = ((sy + 1.0f) * (float)K - 1.0f) * 0.5f;
    int x0 = (int)floorf(fx);
    int y0 = (int)floorf(fy);
    float wx1 = fx - (float)x0;
    float wy1 = fy - (float)y0;
    const float* wo = w + o * KK;

    auto g = [&](int y, int x) -> float {
        if (y < 0 || y >= K || x < 0 || x >= K) return 0.0f;
        return wo[y * K + x];
    };
    float v = g(y0, x0) * (1.0f - wy1) * (1.0f - wx1)
            + g(y0, x0 + 1) * (1.0f - wy1) * wx1
            + g(y0 + 1, x0) * wy1 * (1.0f - wx1)
            + g(y0 + 1, x0 + 1) * wy1 * wx1;
    out[idx] = v;
}

// ============================================================
// K2: group conv + bias + lrelu + alpha-combine into d_xout
//   block: fixed (b, r), 4 output channels, full 48x48 spatial
//   thread: 8 rows x 1 col strip  (288 threads = 6 row-tiles x 48 cols)
// ============================================================
template <int K, int PAD, bool FIRST>
__global__ __launch_bounds__(288) void conv_group(
    const float* __restrict__ x, const float* __restrict__ bias,
    const float* __restrict__ kw, const float* __restrict__ gk) {
    constexpr int XD = NX + 2 * PAD;
    constexpr int XS = XD + 1;
    constexpr int KK = K * K;
    const float* rot = (K == 17) ? d_rot17 : d_rot33;

    __shared__ float xs[XD * XS];
    __shared__ float ws[4 * KK];

    int tid = threadIdx.x;
    int b = blockIdx.y >> 3;
    int r = blockIdx.y & 7;
    int o0 = blockIdx.x * 4;

    const float* xb = x + b * NX * NX;
    for (int idx = tid; idx < XD * XD; idx += 288) {
        int row = idx / XD, col = idx - row * XD;
        int gr = row - PAD, gc = col - PAD;
        float v = 0.0f;
        if (gr >= 0 && gr < NX && gc >= 0 && gc < NX) v = xb[gr * NX + gc];
        xs[row * XS + col] = v;
    }
    const float* rbase = rot + (r * NO + o0) * KK;
    for (int idx = tid; idx < 4 * KK; idx += 288) ws[idx] = rbase[idx];
    __syncthreads();

    int tc = tid % 48;
    int tr0 = (tid / 48) * 8;

    float acc[4][8];
#pragma unroll
    for (int o = 0; o < 4; ++o)
#pragma unroll
        for (int e = 0; e < 8; ++e) acc[o][e] = 0.0f;

#pragma unroll 1
    for (int ky = 0; ky < K; ++ky) {
        const float* xp = xs + (tr0 + ky) * XS + tc;
        const float* wp = ws + ky * K;
        for (int kx = 0; kx < K; ++kx) {
            float xv[8];
#pragma unroll
            for (int dr = 0; dr < 8; ++dr) xv[dr] = xp[dr * XS + kx];
#pragma unroll
            for (int o = 0; o < 4; ++o) {
                float wv = wp[o * KK + kx];
#pragma unroll
                for (int dr = 0; dr < 8; ++dr)
                    acc[o][dr] = fmaf(wv, xv[dr], acc[o][dr]);
            }
        }
    }

    // gumbel-softmax alpha over kernel sizes
    float l0 = (kw[0] + gk[0]) / 10.0f;
    float l1 = (kw[1] + gk[1]) / 10.0f;
    float mm = fmaxf(l0, l1);
    float e0 = expf(l0 - mm), e1 = expf(l1 - mm);
    float alpha = (FIRST ? e0 : e1) / (e0 + e1);

#pragma unroll
    for (int o = 0; o < 4; ++o) {
        float bo = bias[o0 + o];
        float* op = d_xout + (((b * NO + o0 + o) * NR + r) * NHW) + tr0 * 48 + tc;
#pragma unroll
        for (int dr = 0; dr < 8; ++dr) {
            float v = acc[o][dr] + bo;
            v = (v >= 0.0f) ? v : 0.01f * v;
            v *= alpha;
            if (FIRST) op[dr * 48] = v;
            else       op[dr * 48] += v;
        }
    }
}

// ============================================================
// K3: fused conv2(128x128) + lrelu + conva(1) + convz(4) heads
//   block: fixed (b, r, spatial row h); 256 thr = 16 o-grp x 16 n-grp
//   thread: 8 o (stride-16 interleave) x 3 spatial
// ============================================================
template <int BRANCH>
__global__ __launch_bounds__(256) void gemm_attnz(
    const float* __restrict__ w2, const float* __restrict__ b2,
    const float* __restrict__ wa, const float* __restrict__ ba,
    const float* __restrict__ wz, const float* __restrict__ bz) {
    constexpr int RCOUNT = BRANCH ? 8 : 4;
    constexpr int RSTEP = BRANCH ? 1 : 2;
    float* attn_out = BRANCH ? d_attn1 : d_attn0;
    float* z_out = BRANCH ? d_z1 : d_z0;

    __shared__ float ws[128 * 33];   // [o][cc], padded stride 33
    __shared__ float xt[128 * 48];   // [c][n]

    int tid = threadIdx.x;
    int to = tid & 15;
    int tn = tid >> 4;
    int h = blockIdx.x;
    int brs = blockIdx.y;
    int b = brs / RCOUNT;
    int rsub = brs - b * RCOUNT;
    int r = rsub * RSTEP;

    const float* xb = d_xout + ((b * NO) * NR + r) * NHW + h * 48;
    for (int idx = tid; idx < 6144; idx += 256) {
        int c = idx / 48, n = idx - c * 48;
        xt[idx] = xb[c * (NR * NHW) + n];
    }

    float acc[8][3];
#pragma unroll
    for (int oo = 0; oo < 8; ++oo)
#pragma unroll
        for (int j = 0; j < 3; ++j) acc[oo][j] = 0.0f;

    for (int kc = 0; kc < 4; ++kc) {
        __syncthreads();
        for (int idx = tid; idx < 4096; idx += 256) {
            int o = idx >> 5, cc = idx & 31;
            ws[o * 33 + cc] = w2[o * 128 + kc * 32 + cc];
        }
        __syncthreads();
#pragma unroll 4
        for (int cc = 0; cc < 32; ++cc) {
            int k = kc * 32 + cc;
            float xv[3];
#pragma unroll
            for (int j = 0; j < 3; ++j) xv[j] = xt[k * 48 + tn * 3 + j];
#pragma unroll
            for (int oo = 0; oo < 8; ++oo) {
                float wv = ws[(oo * 16 + to) * 33 + cc];
                acc[oo][0] = fmaf(wv, xv[0], acc[oo][0]);
                acc[oo][1] = fmaf(wv, xv[1], acc[oo][1]);
                acc[oo][2] = fmaf(wv, xv[2], acc[oo][2]);
            }
        }
    }

    // epilogue: h = lrelu(acc + b2[o]); heads reduce over o
    float pa[3] = {0.f, 0.f, 0.f};
    float pz[4][3];
#pragma unroll
    for (int l = 0; l < 4; ++l)
#pragma unroll
        for (int j = 0; j < 3; ++j) pz[l][j] = 0.0f;

#pragma unroll
    for (int oo = 0; oo < 8; ++oo) {
        int o = oo * 16 + to;
        float bb = b2[o];
        float wav = wa[o];
        float w0 = wz[o], w1 = wz[128 + o], w2v = wz[256 + o], w3 = wz[384 + o];
#pragma unroll
        for (int j = 0; j < 3; ++j) {
            float hv = acc[oo][j] + bb;
            hv = (hv >= 0.0f) ? hv : 0.01f * hv;
            pa[j] = fmaf(wav, hv, pa[j]);
            pz[0][j] = fmaf(w0, hv, pz[0][j]);
            pz[1][j] = fmaf(w1, hv, pz[1][j]);
            pz[2][j] = fmaf(w2v, hv, pz[2][j]);
            pz[3][j] = fmaf(w3, hv, pz[3][j]);
        }
    }

    // reduce across the 16 o-groups (lanes differing in bits 0..3)
#pragma unroll
    for (int m = 8; m >= 1; m >>= 1) {
#pragma unroll
        for (int j = 0; j < 3; ++j) {
            pa[j] += __shfl_xor_sync(0xffffffffu, pa[j], m);
#pragma unroll
            for (int l = 0; l < 4; ++l)
                pz[l][j] += __shfl_xor_sync(0xffffffffu, pz[l][j], m);
        }
    }

    if (to == 0) {
        int nbase = h * 48 + tn * 3;
#pragma unroll
        for (int j = 0; j < 3; ++j)
            attn_out[(b * RCOUNT + rsub) * NHW + nbase + j] = pa[j] + ba[0];
#pragma unroll
        for (int l = 0; l < 4; ++l)
#pragma unroll
            for (int j = 0; j < 3; ++j)
                z_out[((b * 4 + l) * RCOUNT + rsub) * NHW + nbase + j] =
                    pz[l][j] + bz[l];
    }
}

// ============================================================
// K4: scatter combine (betas) + p_r; writes attn, z, theta,
//     p_r, offsets directly into d_out
// ============================================================
__global__ void combine_kern(const float* __restrict__ rw,
                             const float* __restrict__ gr,
                             float* __restrict__ out) {
    int idx = blockIdx.x * blockDim.x + threadIdx.x;
    if (idx >= NB * NR * NHW) return;

    float l0 = (rw[0] + gr[0]) / 10.0f;
    float l1 = (rw[1] + gr[1]) / 10.0f;
    float mm = fmaxf(l0, l1);
    float e0 = expf(l0 - mm), e1 = expf(l1 - mm);
    float inv = 1.0f / (e0 + e1);
    float b0 = e0 * inv, b1 = e1 * inv;

    int b = idx / (NR * NHW);
    int rem = idx - b * (NR * NHW);
    int r = rem / NHW;
    int hw = rem - r * NHW;
    float off = c_offs[r];
    float t = off / PI_F;
    float pr = -0.5f * t * t - LOG_SIGMA - HALF_LOG2PI;

    float a = b1 * d_attn1[(b * NR + r) * NHW + hw];
    bool even = ((r & 1) == 0);
    if (even) a += b0 * d_attn0[(b * 4 + (r >> 1)) * NHW + hw];
    a += pr;
    out[OFF_ATTN + idx] = a;

    float zv[4];
#pragma unroll
    for (int l = 0; l < 4; ++l) {
        float z = b1 * d_z1[((b * 4 + l) * NR + r) * NHW + hw];
        if (even) z += b0 * d_z0[((b * 4 + l) * 4 + (r >> 1)) * NHW + hw];
        zv[l] = z;
        out[OFF_Z + ((b * 4 + l) * NR + r) * NHW + hw] = z;
    }
    out[OFF_TH + ((b * 2 + 0) * NR + r) * NHW + hw] = zv[0] + off;
    out[OFF_TH + ((b * 2 + 1) * NR + r) * NHW + hw] = zv[1];

    if (idx < 8) {
        float o2 = c_offs[idx];
        float t2 = o2 / PI_F;
        out[OFF_PR + idx] = -0.5f * t2 * t2 - LOG_SIGMA - HALF_LOG2PI;
        out[OFF_OFF + idx] = o2;
    }
}

// ============================================================
// K5: per-batch softmax stats (max / sumexp, two distributions)
// ============================================================
__global__ void stats_kern(const float* __restrict__ out,
                           const float* __restrict__ g) {
    __shared__ float sm[256];
    int b = blockIdx.x, tid = threadIdx.x;
    const float* a = out + OFF_ATTN + b * (NR * NHW);
    const float* gb = g + b * (NR * NHW);

    float m1 = -1e30f, m2 = -1e30f;
    for (int i = tid; i < NR * NHW; i += 256) {
        float v = a[i];
        m1 = fmaxf(m1, v);
        m2 = fmaxf(m2, v + gb[i]);
    }
    sm[tid] = m1; __syncthreads();
    for (int s = 128; s > 0; s >>= 1) {
        if (tid < s) sm[tid] = fmaxf(sm[tid], sm[tid + s]);
        __syncthreads();
    }
    m1 = sm[0]; __syncthreads();
    sm[tid] = m2; __syncthreads();
    for (int s = 128; s > 0; s >>= 1) {
        if (tid < s) sm[tid] = fmaxf(sm[tid], sm[tid + s]);
        __syncthreads();
    }
    m2 = sm[0]; __syncthreads();

    float s1 = 0.0f, s2 = 0.0f;
    for (int i = tid; i < NR * NHW; i += 256) {
        float v = a[i];
        s1 += expf(v - m1);
        s2 += expf(v + gb[i] - m2);
    }
    sm[tid] = s1; __syncthreads();
    for (int s = 128; s > 0; s >>= 1) {
        if (tid < s) sm[tid] += sm[tid + s];
        __syncthreads();
    }
    s1 = sm[0]; __syncthreads();
    sm[tid] = s2; __syncthreads();
    for (int s = 128; s > 0; s >>= 1) {
        if (tid < s) sm[tid] += sm[tid + s];
        __syncthreads();
    }
    s2 = sm[0];

    if (tid == 0) {
        d_stats[b * 4 + 0] = m1;
        d_stats[b * 4 + 1] = s1;
        d_stats[b * 4 + 2] = m2;
        d_stats[b * 4 + 3] = s2;
    }
}

// ============================================================
// K6: q_t_r (log_softmax) + a_sampled (gumbel softmax)
// ============================================================
__global__ void final_kern(const float* __restrict__ g,
                           float* __restrict__ out) {
    int idx = blockIdx.x * blockDim.x + threadIdx.x;
    if (idx >= NB * NR * NHW) return;
    int b = idx / (NR * NHW);
    float v = out[OFF_ATTN + idx];
    out[OFF_Q + idx] = (v - d_stats[b * 4 + 0]) - logf(d_stats[b * 4 + 1]);
    out[OFF_A + idx] =
        expf(v + g[idx] - d_stats[b * 4 + 2]) / d_stats[b * 4 + 3];
}

// ============================================================
extern "C" void kernel_launch(void* const* d_in, const int* in_sizes, int n_in,
                              void* d_out, int out_size) {
    const float* x   = (const float*)d_in[0];
    const float* ksw = (const float*)d_in[1];
    const float* rdw = (const float*)d_in[2];
    const float* w17 = (const float*)d_in[3];
    const float* b17 = (const float*)d_in[4];
    const float* w33 = (const float*)d_in[5];
    const float* b33 = (const float*)d_in[6];
    const float* w2  = (const float*)d_in[7];
    const float* b2  = (const float*)d_in[8];
    const float* wa  = (const float*)d_in[9];
    const float* ba  = (const float*)d_in[10];
    const float* wz  = (const float*)d_in[11];
    const float* bz  = (const float*)d_in[12];
    const float* gk  = (const float*)d_in[13];
    const float* gr  = (const float*)d_in[14];
    const float* ga  = (const float*)d_in[15];
    float* out = (float*)d_out;

    rotate_kern<17><<<(NR * NO * 289 + 255) / 256, 256>>>(w17);
    rotate_kern<33><<<(NR * NO * 1089 + 255) / 256, 256>>>(w33);

    conv_group<17, 0, true ><<<dim3(32, 64), 288>>>(x, b17, ksw, gk);
    conv_group<33, 8, false><<<dim3(32, 64), 288>>>(x, b33, ksw, gk);

    gemm_attnz<1><<<dim3(48, 64), 256>>>(w2 + 16384, b2 + 128, wa + 128,
                                         ba + 1, wz + 512, bz + 4);
    gemm_attnz<0><<<dim3(48, 32), 256>>>(w2, b2, wa, ba, wz, bz);

    combine_kern<<<(NB * NR * NHW + 255) / 256, 256>>>(rdw, gr, out);
    stats_kern<<<NB, 256>>>(out, ga);
    final_kern<<<(NB * NR * NHW + 255) / 256, 256>>>(ga, out);
}

// round 3
// speedup vs baseline: 1.0016x; 1.0016x over previous
#include <cuda_runtime.h>
#include <math.h>

#define NB 8
#define NO 128
#define NR 8
#define NH 48
#define NHW 2304
#define NX 64

// ---- output layout (concatenated flattened outputs, float32) ----
#define OFF_ATTN 0
#define OFF_Q    147456
#define OFF_PR   294912
#define OFF_A    294920
#define OFF_OFF  442376
#define OFF_TH   442384
#define OFF_Z    737296

// ---- device scratch (static, no runtime allocation) ----
__device__ float d_rot17[NR * NO * 17 * 17];
__device__ float d_rot33[NR * NO * 33 * 33];
__device__ float d_xout[NB * NO * NR * NHW];     // [b][c][r][hw]
__device__ float d_attn1[NB * NR * NHW];
__device__ float d_attn0[NB * 4 * NHW];
__device__ float d_z1[NB * 4 * NR * NHW];        // [b][l][r][hw]
__device__ float d_z0[NB * 4 * 4 * NHW];
__device__ float d_stats[NB * 4];                // m1, s1, m2, s2

__constant__ float c_offs[8] = {
    0.0f, 0.7853981633974483f, 1.5707963267948966f, 2.356194490192345f,
    3.141592653589793f, -2.356194490192345f, -1.5707963267948966f,
    -0.7853981633974483f};

#define LOG_SIGMA   1.1447298858494002f   // log(pi), f32
#define HALF_LOG2PI 0.9189385332046727f   // 0.5*log(2*pi), f32
#define PI_F        3.14159265358979323846f

// ============================================================
// K1: rotate kernels (bilinear grid_sample semantics, zero pad)
// ============================================================
template <int K>
__global__ void rotate_kern(const float* __restrict__ w) {
    constexpr int KK = K * K;
    float* out = (K == 17) ? d_rot17 : d_rot33;
    int idx = blockIdx.x * blockDim.x + threadIdx.x;
    if (idx >= NR * NO * KK) return;
    int j = idx % K;
    int t = idx / K;
    int i = t % K; t /= K;
    int o = t % NO;
    int r = t / NO;

    float theta = 0.7853981633974483f * (float)r;  // (2*pi/8)*r in f32
    float c = cosf(theta), s = sinf(theta);
    float gy = (2.0f * (float)i + 1.0f) / (float)K - 1.0f;
    float gx = (2.0f * (float)j + 1.0f) / (float)K - 1.0f;
    float sx = c * gx - s * gy;
    float sy = s * gx + c * gy;
    float fx = ((sx + 1.0f) * (float)K - 1.0f) * 0.5f;
    float fy = ((sy + 1.0f) * (float)K - 1.0f) * 0.5f;
    int x0 = (int)floorf(fx);
    int y0 = (int)floorf(fy);
    float wx1 = fx - (float)x0;
    float wy1 = fy - (float)y0;
    const float* wo = w + o * KK;

    auto g = [&](int y, int x) -> float {
        if (y < 0 || y >= K || x < 0 || x >= K) return 0.0f;
        return wo[y * K + x];
    };
    float v = g(y0, x0) * (1.0f - wy1) * (1.0f - wx1)
            + g(y0, x0 + 1) * (1.0f - wy1) * wx1
            + g(y0 + 1, x0) * wy1 * (1.0f - wx1)
            + g(y0 + 1, x0 + 1) * wy1 * wx1;
    out[idx] = v;
}

// ============================================================
// K2: group conv + bias + lrelu + alpha-combine into d_xout
//   block: fixed (b, r), 4 output channels, full 48x48 spatial
//   thread: 8 rows x 1 col strip  (288 threads = 6 row-tiles x 48 cols)
// ============================================================
template <int K, int PAD, bool FIRST>
__global__ __launch_bounds__(288) void conv_group(
    const float* __restrict__ x, const float* __restrict__ bias,
    const float* __restrict__ kw, const float* __restrict__ gk) {
    constexpr int XD = NX + 2 * PAD;
    constexpr int XS = XD + 1;
    constexpr int KK = K * K;
    const float* rot = (K == 17) ? d_rot17 : d_rot33;

    __shared__ float xs[XD * XS];
    __shared__ float ws[4 * KK];

    int tid = threadIdx.x;
    int b = blockIdx.y >> 3;
    int r = blockIdx.y & 7;
    int o0 = blockIdx.x * 4;

    const float* xb = x + b * NX * NX;
    for (int idx = tid; idx < XD * XD; idx += 288) {
        int row = idx / XD, col = idx - row * XD;
        int gr = row - PAD, gc = col - PAD;
        float v = 0.0f;
        if (gr >= 0 && gr < NX && gc >= 0 && gc < NX) v = xb[gr * NX + gc];
        xs[row * XS + col] = v;
    }
    const float* rbase = rot + (r * NO + o0) * KK;
    for (int idx = tid; idx < 4 * KK; idx += 288) ws[idx] = rbase[idx];
    __syncthreads();

    int tc = tid % 48;
    int tr0 = (tid / 48) * 8;

    float acc[4][8];
#pragma unroll
    for (int o = 0; o < 4; ++o)
#pragma unroll
        for (int e = 0; e < 8; ++e) acc[o][e] = 0.0f;

#pragma unroll 1
    for (int ky = 0; ky < K; ++ky) {
        const float* xp = xs + (tr0 + ky) * XS + tc;
        const float* wp = ws + ky * K;
        for (int kx = 0; kx < K; ++kx) {
            float xv[8];
#pragma unroll
            for (int dr = 0; dr < 8; ++dr) xv[dr] = xp[dr * XS + kx];
#pragma unroll
            for (int o = 0; o < 4; ++o) {
                float wv = wp[o * KK + kx];
#pragma unroll
                for (int dr = 0; dr < 8; ++dr)
                    acc[o][dr] = fmaf(wv, xv[dr], acc[o][dr]);
            }
        }
    }

    // gumbel-softmax alpha over kernel sizes
    float l0 = (kw[0] + gk[0]) / 10.0f;
    float l1 = (kw[1] + gk[1]) / 10.0f;
    float mm = fmaxf(l0, l1);
    float e0 = expf(l0 - mm), e1 = expf(l1 - mm);
    float alpha = (FIRST ? e0 : e1) / (e0 + e1);

#pragma unroll
    for (int o = 0; o < 4; ++o) {
        float bo = bias[o0 + o];
        float* op = d_xout + (((b * NO + o0 + o) * NR + r) * NHW) + tr0 * 48 + tc;
#pragma unroll
        for (int dr = 0; dr < 8; ++dr) {
            float v = acc[o][dr] + bo;
            v = (v >= 0.0f) ? v : 0.01f * v;
            v *= alpha;
            if (FIRST) op[dr * 48] = v;
            else       op[dr * 48] += v;
        }
    }
}

// ============================================================
// K3: fused conv2(128x128) + lrelu + conva(1) + convz(4) heads
//   block: fixed (b, r, spatial row h); 256 thr = 16 o-grp x 16 n-grp
//   thread: 8 o (stride-16 interleave) x 3 spatial
// ============================================================
template <int BRANCH>
__global__ __launch_bounds__(256) void gemm_attnz(
    const float* __restrict__ w2, const float* __restrict__ b2,
    const float* __restrict__ wa, const float* __restrict__ ba,
    const float* __restrict__ wz, const float* __restrict__ bz) {
    constexpr int RCOUNT = BRANCH ? 8 : 4;
    constexpr int RSTEP = BRANCH ? 1 : 2;
    float* attn_out = BRANCH ? d_attn1 : d_attn0;
    float* z_out = BRANCH ? d_z1 : d_z0;

    __shared__ float ws[128 * 33];   // [o][cc], padded stride 33
    __shared__ float xt[128 * 48];   // [c][n]

    int tid = threadIdx.x;
    int to = tid & 15;
    int tn = tid >> 4;
    int h = blockIdx.x;
    int brs = blockIdx.y;
    int b = brs / RCOUNT;
    int rsub = brs - b * RCOUNT;
    int r = rsub * RSTEP;

    const float* xb = d_xout + ((b * NO) * NR + r) * NHW + h * 48;
    for (int idx = tid; idx < 6144; idx += 256) {
        int c = idx / 48, n = idx - c * 48;
        xt[idx] = xb[c * (NR * NHW) + n];
    }

    float acc[8][3];
#pragma unroll
    for (int oo = 0; oo < 8; ++oo)
#pragma unroll
        for (int j = 0; j < 3; ++j) acc[oo][j] = 0.0f;

    for (int kc = 0; kc < 4; ++kc) {
        __syncthreads();
        for (int idx = tid; idx < 4096; idx += 256) {
            int o = idx >> 5, cc = idx & 31;
            ws[o * 33 + cc] = w2[o * 128 + kc * 32 + cc];
        }
        __syncthreads();
#pragma unroll 4
        for (int cc = 0; cc < 32; ++cc) {
            int k = kc * 32 + cc;
            float xv[3];
#pragma unroll
            for (int j = 0; j < 3; ++j) xv[j] = xt[k * 48 + tn * 3 + j];
#pragma unroll
            for (int oo = 0; oo < 8; ++oo) {
                float wv = ws[(oo * 16 + to) * 33 + cc];
                acc[oo][0] = fmaf(wv, xv[0], acc[oo][0]);
                acc[oo][1] = fmaf(wv, xv[1], acc[oo][1]);
                acc[oo][2] = fmaf(wv, xv[2], acc[oo][2]);
            }
        }
    }

    // epilogue: h = lrelu(acc + b2[o]); heads reduce over o
    float pa[3] = {0.f, 0.f, 0.f};
    float pz[4][3];
#pragma unroll
    for (int l = 0; l < 4; ++l)
#pragma unroll
        for (int j = 0; j < 3; ++j) pz[l][j] = 0.0f;

#pragma unroll
    for (int oo = 0; oo < 8; ++oo) {
        int o = oo * 16 + to;
        float bb = b2[o];
        float wav = wa[o];
        float w0 = wz[o], w1 = wz[128 + o], w2v = wz[256 + o], w3 = wz[384 + o];
#pragma unroll
        for (int j = 0; j < 3; ++j) {
            float hv = acc[oo][j] + bb;
            hv = (hv >= 0.0f) ? hv : 0.01f * hv;
            pa[j] = fmaf(wav, hv, pa[j]);
            pz[0][j] = fmaf(w0, hv, pz[0][j]);
            pz[1][j] = fmaf(w1, hv, pz[1][j]);
            pz[2][j] = fmaf(w2v, hv, pz[2][j]);
            pz[3][j] = fmaf(w3, hv, pz[3][j]);
        }
    }

    // reduce across the 16 o-groups (lanes differing in bits 0..3)
#pragma unroll
    for (int m = 8; m >= 1; m >>= 1) {
#pragma unroll
        for (int j = 0; j < 3; ++j) {
            pa[j] += __shfl_xor_sync(0xffffffffu, pa[j], m);
#pragma unroll
            for (int l = 0; l < 4; ++l)
                pz[l][j] += __shfl_xor_sync(0xffffffffu, pz[l][j], m);
        }
    }

    if (to == 0) {
        int nbase = h * 48 + tn * 3;
#pragma unroll
        for (int j = 0; j < 3; ++j)
            attn_out[(b * RCOUNT + rsub) * NHW + nbase + j] = pa[j] + ba[0];
#pragma unroll
        for (int l = 0; l < 4; ++l)
#pragma unroll
            for (int j = 0; j < 3; ++j)
                z_out[((b * 4 + l) * RCOUNT + rsub) * NHW + nbase + j] =
                    pz[l][j] + bz[l];
    }
}

// ============================================================
// K4: scatter combine (betas) + p_r; writes attn, z, theta,
//     p_r, offsets directly into d_out
// ============================================================
__global__ void combine_kern(const float* __restrict__ rw,
                             const float* __restrict__ gr,
                             float* __restrict__ out) {
    int idx = blockIdx.x * blockDim.x + threadIdx.x;
    if (idx >= NB * NR * NHW) return;

    float l0 = (rw[0] + gr[0]) / 10.0f;
    float l1 = (rw[1] + gr[1]) / 10.0f;
    float mm = fmaxf(l0, l1);
    float e0 = expf(l0 - mm), e1 = expf(l1 - mm);
    float inv = 1.0f / (e0 + e1);
    float b0 = e0 * inv, b1 = e1 * inv;

    int b = idx / (NR * NHW);
    int rem = idx - b * (NR * NHW);
    int r = rem / NHW;
    int hw = rem - r * NHW;
    float off = c_offs[r];
    float t = off / PI_F;
    float pr = -0.5f * t * t - LOG_SIGMA - HALF_LOG2PI;

    float a = b1 * d_attn1[(b * NR + r) * NHW + hw];
    bool even = ((r & 1) == 0);
    if (even) a += b0 * d_attn0[(b * 4 + (r >> 1)) * NHW + hw];
    a += pr;
    out[OFF_ATTN + idx] = a;

    float zv[4];
#pragma unroll
    for (int l = 0; l < 4; ++l) {
        float z = b1 * d_z1[((b * 4 + l) * NR + r) * NHW + hw];
        if (even) z += b0 * d_z0[((b * 4 + l) * 4 + (r >> 1)) * NHW + hw];
        zv[l] = z;
        out[OFF_Z + ((b * 4 + l) * NR + r) * NHW + hw] = z;
    }
    out[OFF_TH + ((b * 2 + 0) * NR + r) * NHW + hw] = zv[0] + off;
    out[OFF_TH + ((b * 2 + 1) * NR + r) * NHW + hw] = zv[1];

    if (idx < 8) {
        float o2 = c_offs[idx];
        float t2 = o2 / PI_F;
        out[OFF_PR + idx] = -0.5f * t2 * t2 - LOG_SIGMA - HALF_LOG2PI;
        out[OFF_OFF + idx] = o2;
    }
}

// ============================================================
// K5: per-batch softmax stats (max / sumexp, two distributions)
// ============================================================
__global__ void stats_kern(const float* __restrict__ out,
                           const float* __restrict__ g) {
    __shared__ float sm[256];
    int b = blockIdx.x, tid = threadIdx.x;
    const float* a = out + OFF_ATTN + b * (NR * NHW);
    const float* gb = g + b * (NR * NHW);

    float m1 = -1e30f, m2 = -1e30f;
    for (int i = tid; i < NR * NHW; i += 256) {
        float v = a[i];
        m1 = fmaxf(m1, v);
        m2 = fmaxf(m2, v + gb[i]);
    }
    sm[tid] = m1; __syncthreads();
    for (int s = 128; s > 0; s >>= 1) {
        if (tid < s) sm[tid] = fmaxf(sm[tid], sm[tid + s]);
        __syncthreads();
    }
    m1 = sm[0]; __syncthreads();
    sm[tid] = m2; __syncthreads();
    for (int s = 128; s > 0; s >>= 1) {
        if (tid < s) sm[tid] = fmaxf(sm[tid], sm[tid + s]);
        __syncthreads();
    }
    m2 = sm[0]; __syncthreads();

    float s1 = 0.0f, s2 = 0.0f;
    for (int i = tid; i < NR * NHW; i += 256) {
        float v = a[i];
        s1 += expf(v - m1);
        s2 += expf(v + gb[i] - m2);
    }
    sm[tid] = s1; __syncthreads();
    for (int s = 128; s > 0; s >>= 1) {
        if (tid < s) sm[tid] += sm[tid + s];
        __syncthreads();
    }
    s1 = sm[0]; __syncthreads();
    sm[tid] = s2; __syncthreads();
    for (int s = 128; s > 0; s >>= 1) {
        if (tid < s) sm[tid] += sm[tid + s];
        __syncthreads();
    }
    s2 = sm[0];

    if (tid == 0) {
        d_stats[b * 4 + 0] = m1;
        d_stats[b * 4 + 1] = s1;
        d_stats[b * 4 + 2] = m2;
        d_stats[b * 4 + 3] = s2;
    }
}

// ============================================================
// K6: q_t_r (log_softmax) + a_sampled (gumbel softmax)
// ============================================================
__global__ void final_kern(const float* __restrict__ g,
                           float* __restrict__ out) {
    int idx = blockIdx.x * blockDim.x + threadIdx.x;
    if (idx >= NB * NR * NHW) return;
    int b = idx / (NR * NHW);
    float v = out[OFF_ATTN + idx];
    out[OFF_Q + idx] = (v - d_stats[b * 4 + 0]) - logf(d_stats[b * 4 + 1]);
    out[OFF_A + idx] =
        expf(v + g[idx] - d_stats[b * 4 + 2]) / d_stats[b * 4 + 3];
}

// ============================================================
extern "C" void kernel_launch(void* const* d_in, const int* in_sizes, int n_in,
                              void* d_out, int out_size) {
    const float* x   = (const float*)d_in[0];
    const float* ksw = (const float*)d_in[1];
    const float* rdw = (const float*)d_in[2];
    const float* w17 = (const float*)d_in[3];
    const float* b17 = (const float*)d_in[4];
    const float* w33 = (const float*)d_in[5];
    const float* b33 = (const float*)d_in[6];
    const float* w2  = (const float*)d_in[7];
    const float* b2  = (const float*)d_in[8];
    const float* wa  = (const float*)d_in[9];
    const float* ba  = (const float*)d_in[10];
    const float* wz  = (const float*)d_in[11];
    const float* bz  = (const float*)d_in[12];
    const float* gk  = (const float*)d_in[13];
    const float* gr  = (const float*)d_in[14];
    const float* ga  = (const float*)d_in[15];
    float* out = (float*)d_out;

    rotate_kern<17><<<(NR * NO * 289 + 255) / 256, 256>>>(w17);
    rotate_kern<33><<<(NR * NO * 1089 + 255) / 256, 256>>>(w33);

    conv_group<17, 0, true ><<<dim3(32, 64), 288>>>(x, b17, ksw, gk);
    conv_group<33, 8, false><<<dim3(32, 64), 288>>>(x, b33, ksw, gk);

    gemm_attnz<1><<<dim3(48, 64), 256>>>(w2 + 16384, b2 + 128, wa + 128,
                                         ba + 1, wz + 512, bz + 4);
    gemm_attnz<0><<<dim3(48, 32), 256>>>(w2, b2, wa, ba, wz, bz);

    combine_kern<<<(NB * NR * NHW + 255) / 256, 256>>>(rdw, gr, out);
    stats_kern<<<NB, 256>>>(out, ga);
    final_kern<<<(NB * NR * NHW + 255) / 256, 256>>>(ga, out);
}

// round 4
// speedup vs baseline: 1.1065x; 1.1048x over previous
#include <cuda_runtime.h>
#include <math.h>

#define NB 8
#define NO 128
#define NR 8
#define NH 48
#define NHW 2304
#define NX 64

// ---- output layout (concatenated flattened outputs, float32) ----
#define OFF_ATTN 0
#define OFF_Q    147456
#define OFF_PR   294912
#define OFF_A    294920
#define OFF_OFF  442376
#define OFF_TH   442384
#define OFF_Z    737296

// ---- device scratch (static, no runtime allocation) ----
__device__ float d_rot17[NR * NO * 17 * 17];
__device__ float d_rot33[NR * NO * 33 * 33];
__device__ float d_xout[NB * NO * NR * NHW];     // [b][c][r][hw]
__device__ float d_attn1[NB * NR * NHW];
__device__ float d_attn0[NB * 4 * NHW];
__device__ float d_z1[NB * 4 * NR * NHW];        // [b][l][r][hw]
__device__ float d_z0[NB * 4 * 4 * NHW];
__device__ float d_stats[NB * 4];                // m1, s1, m2, s2

__constant__ float c_offs[8] = {
    0.0f, 0.7853981633974483f, 1.5707963267948966f, 2.356194490192345f,
    3.141592653589793f, -2.356194490192345f, -1.5707963267948966f,
    -0.7853981633974483f};

#define LOG_SIGMA   1.1447298858494002f   // log(pi), f32
#define HALF_LOG2PI 0.9189385332046727f   // 0.5*log(2*pi), f32
#define PI_F        3.14159265358979323846f

// packed f32x2 helpers (FFMA2 is PTX-only; ptxas never auto-fuses)
#define FFMA2(acc, a, b) \
    asm("fma.rn.f32x2 %0, %1, %2, %0;" : "+l"(acc) : "l"(a), "l"(b))
#define PACK2(dst, lo, hi) \
    asm("mov.b64 %0, {%1, %2};" : "=l"(dst) : "f"(lo), "f"(hi))
#define UNPACK2(lo, hi, src) \
    asm("mov.b64 {%0, %1}, %2;" : "=f"(lo), "=f"(hi) : "l"(src))

// ============================================================
// K1: rotate kernels (bilinear grid_sample semantics, zero pad)
// ============================================================
template <int K>
__global__ void rotate_kern(const float* __restrict__ w) {
    constexpr int KK = K * K;
    float* out = (K == 17) ? d_rot17 : d_rot33;
    int idx = blockIdx.x * blockDim.x + threadIdx.x;
    if (idx >= NR * NO * KK) return;
    int j = idx % K;
    int t = idx / K;
    int i = t % K; t /= K;
    int o = t % NO;
    int r = t / NO;

    float theta = 0.7853981633974483f * (float)r;  // (2*pi/8)*r in f32
    float c = cosf(theta), s = sinf(theta);
    float gy = (2.0f * (float)i + 1.0f) / (float)K - 1.0f;
    float gx = (2.0f * (float)j + 1.0f) / (float)K - 1.0f;
    float sx = c * gx - s * gy;
    float sy = s * gx + c * gy;
    float fx = ((sx + 1.0f) * (float)K - 1.0f) * 0.5f;
    float fy = ((sy + 1.0f) * (float)K - 1.0f) * 0.5f;
    int x0 = (int)floorf(fx);
    int y0 = (int)floorf(fy);
    float wx1 = fx - (float)x0;
    float wy1 = fy - (float)y0;
    const float* wo = w + o * KK;

    auto g = [&](int y, int x) -> float {
        if (y < 0 || y >= K || x < 0 || x >= K) return 0.0f;
        return wo[y * K + x];
    };
    float v = g(y0, x0) * (1.0f - wy1) * (1.0f - wx1)
            + g(y0, x0 + 1) * (1.0f - wy1) * wx1
            + g(y0 + 1, x0) * wy1 * (1.0f - wx1)
            + g(y0 + 1, x0 + 1) * wy1 * wx1;
    out[idx] = v;
}

// ============================================================
// K2: group conv + bias + lrelu + alpha-combine into d_xout
//   block: fixed (b, r), 8 output channels, full 48x48 spatial
//   thread: 8 rows x 1 col strip; accumulators packed as f32x2
//   weights in smem pre-duplicated (w,w) -> one LDS.64 broadcast,
//   main loop runs fma.rn.f32x2 (2 FMA/instr).
// ============================================================
template <int K, int PAD, bool FIRST>
__global__ __launch_bounds__(288) void conv_group(
    const float* __restrict__ x, const float* __restrict__ bias,
    const float* __restrict__ kw, const float* __restrict__ gk) {
    constexpr int XD = NX + 2 * PAD;
    constexpr int XS = XD + 2;          // even stride: rows hit disjoint banks
    constexpr int KK = K * K;
    const float* rot = (K == 17) ? d_rot17 : d_rot33;

    extern __shared__ float smem_dyn[];
    float* xs = smem_dyn;                                       // XD*XS floats
    unsigned long long* ws2 =
        (unsigned long long*)(smem_dyn + XD * XS);              // 8*KK pairs

    int tid = threadIdx.x;
    int b = blockIdx.y >> 3;
    int r = blockIdx.y & 7;
    int o0 = blockIdx.x * 8;

    const float* xb = x + b * NX * NX;
    for (int idx = tid; idx < XD * XD; idx += 288) {
        int row = idx / XD, col = idx - row * XD;
        int gr = row - PAD, gc = col - PAD;
        float v = 0.0f;
        if (gr >= 0 && gr < NX && gc >= 0 && gc < NX) v = xb[gr * NX + gc];
        xs[row * XS + col] = v;
    }
    const float* rbase = rot + (r * NO + o0) * KK;
    for (int idx = tid; idx < 8 * KK; idx += 288) {
        float v = rbase[idx];
        unsigned long long p;
        PACK2(p, v, v);
        ws2[idx] = p;
    }
    __syncthreads();

    int tc = tid % 48;
    int tr0 = (tid / 48) * 8;

    unsigned long long acc[8][4];
#pragma unroll
    for (int o = 0; o < 8; ++o)
#pragma unroll
        for (int p = 0; p < 4; ++p) acc[o][p] = 0ull;

#pragma unroll 1
    for (int ky = 0; ky < K; ++ky) {
        const float* xp = xs + (tr0 + ky) * XS + tc;
        const unsigned long long* wp = ws2 + ky * K;
#pragma unroll 3
        for (int kx = 0; kx < K; ++kx) {
            unsigned long long xv[4];
#pragma unroll
            for (int p = 0; p < 4; ++p) {
                float lo = xp[(2 * p) * XS + kx];
                float hi = xp[(2 * p + 1) * XS + kx];
                PACK2(xv[p], lo, hi);
            }
#pragma unroll
            for (int o = 0; o < 8; ++o) {
                unsigned long long wv = wp[o * KK + kx];  // LDS.64 broadcast
                FFMA2(acc[o][0], wv, xv[0]);
                FFMA2(acc[o][1], wv, xv[1]);
                FFMA2(acc[o][2], wv, xv[2]);
                FFMA2(acc[o][3], wv, xv[3]);
            }
        }
    }

    // gumbel-softmax alpha over kernel sizes
    float l0 = (kw[0] + gk[0]) / 10.0f;
    float l1 = (kw[1] + gk[1]) / 10.0f;
    float mm = fmaxf(l0, l1);
    float e0 = expf(l0 - mm), e1 = expf(l1 - mm);
    float alpha = (FIRST ? e0 : e1) / (e0 + e1);

#pragma unroll
    for (int o = 0; o < 8; ++o) {
        float bo = bias[o0 + o];
        float* op = d_xout + (((b * NO + o0 + o) * NR + r) * NHW) + tr0 * 48 + tc;
#pragma unroll
        for (int p = 0; p < 4; ++p) {
            float v0, v1;
            UNPACK2(v0, v1, acc[o][p]);
            v0 += bo;
            v1 += bo;
            v0 = (v0 >= 0.0f) ? v0 : 0.01f * v0;
            v1 = (v1 >= 0.0f) ? v1 : 0.01f * v1;
            v0 *= alpha;
            v1 *= alpha;
            if (FIRST) {
                op[(2 * p) * 48] = v0;
                op[(2 * p + 1) * 48] = v1;
            } else {
                op[(2 * p) * 48] += v0;
                op[(2 * p + 1) * 48] += v1;
            }
        }
    }
}

// ============================================================
// K3: fused conv2(128x128) + lrelu + conva(1) + convz(4) heads
//   block: fixed (b, r, spatial row h); 256 thr = 16 o-grp x 16 n-grp
//   thread: 8 o (stride-16 interleave) x 3 spatial
// ============================================================
template <int BRANCH>
__global__ __launch_bounds__(256) void gemm_attnz(
    const float* __restrict__ w2, const float* __restrict__ b2,
    const float* __restrict__ wa, const float* __restrict__ ba,
    const float* __restrict__ wz, const float* __restrict__ bz) {
    constexpr int RCOUNT = BRANCH ? 8 : 4;
    constexpr int RSTEP = BRANCH ? 1 : 2;
    float* attn_out = BRANCH ? d_attn1 : d_attn0;
    float* z_out = BRANCH ? d_z1 : d_z0;

    __shared__ float ws[128 * 33];   // [o][cc], padded stride 33
    __shared__ float xt[128 * 48];   // [c][n]

    int tid = threadIdx.x;
    int to = tid & 15;
    int tn = tid >> 4;
    int h = blockIdx.x;
    int brs = blockIdx.y;
    int b = brs / RCOUNT;
    int rsub = brs - b * RCOUNT;
    int r = rsub * RSTEP;

    const float* xb = d_xout + ((b * NO) * NR + r) * NHW + h * 48;
    for (int idx = tid; idx < 6144; idx += 256) {
        int c = idx / 48, n = idx - c * 48;
        xt[idx] = xb[c * (NR * NHW) + n];
    }

    float acc[8][3];
#pragma unroll
    for (int oo = 0; oo < 8; ++oo)
#pragma unroll
        for (int j = 0; j < 3; ++j) acc[oo][j] = 0.0f;

    for (int kc = 0; kc < 4; ++kc) {
        __syncthreads();
        for (int idx = tid; idx < 4096; idx += 256) {
            int o = idx >> 5, cc = idx & 31;
            ws[o * 33 + cc] = w2[o * 128 + kc * 32 + cc];
        }
        __syncthreads();
#pragma unroll 4
        for (int cc = 0; cc < 32; ++cc) {
            int k = kc * 32 + cc;
            float xv[3];
#pragma unroll
            for (int j = 0; j < 3; ++j) xv[j] = xt[k * 48 + tn * 3 + j];
#pragma unroll
            for (int oo = 0; oo < 8; ++oo) {
                float wv = ws[(oo * 16 + to) * 33 + cc];
                acc[oo][0] = fmaf(wv, xv[0], acc[oo][0]);
                acc[oo][1] = fmaf(wv, xv[1], acc[oo][1]);
                acc[oo][2] = fmaf(wv, xv[2], acc[oo][2]);
            }
        }
    }

    // epilogue: h = lrelu(acc + b2[o]); heads reduce over o
    float pa[3] = {0.f, 0.f, 0.f};
    float pz[4][3];
#pragma unroll
    for (int l = 0; l < 4; ++l)
#pragma unroll
        for (int j = 0; j < 3; ++j) pz[l][j] = 0.0f;

#pragma unroll
    for (int oo = 0; oo < 8; ++oo) {
        int o = oo * 16 + to;
        float bb = b2[o];
        float wav = wa[o];
        float w0 = wz[o], w1 = wz[128 + o], w2v = wz[256 + o], w3 = wz[384 + o];
#pragma unroll
        for (int j = 0; j < 3; ++j) {
            float hv = acc[oo][j] + bb;
            hv = (hv >= 0.0f) ? hv : 0.01f * hv;
            pa[j] = fmaf(wav, hv, pa[j]);
            pz[0][j] = fmaf(w0, hv, pz[0][j]);
            pz[1][j] = fmaf(w1, hv, pz[1][j]);
            pz[2][j] = fmaf(w2v, hv, pz[2][j]);
            pz[3][j] = fmaf(w3, hv, pz[3][j]);
        }
    }

    // reduce across the 16 o-groups (lanes differing in bits 0..3)
#pragma unroll
    for (int m = 8; m >= 1; m >>= 1) {
#pragma unroll
        for (int j = 0; j < 3; ++j) {
            pa[j] += __shfl_xor_sync(0xffffffffu, pa[j], m);
#pragma unroll
            for (int l = 0; l < 4; ++l)
                pz[l][j] += __shfl_xor_sync(0xffffffffu, pz[l][j], m);
        }
    }

    if (to == 0) {
        int nbase = h * 48 + tn * 3;
#pragma unroll
        for (int j = 0; j < 3; ++j)
            attn_out[(b * RCOUNT + rsub) * NHW + nbase + j] = pa[j] + ba[0];
#pragma unroll
        for (int l = 0; l < 4; ++l)
#pragma unroll
            for (int j = 0; j < 3; ++j)
                z_out[((b * 4 + l) * RCOUNT + rsub) * NHW + nbase + j] =
                    pz[l][j] + bz[l];
    }
}

// ============================================================
// K4: scatter combine (betas) + p_r; writes attn, z, theta,
//     p_r, offsets directly into d_out
// ============================================================
__global__ void combine_kern(const float* __restrict__ rw,
                             const float* __restrict__ gr,
                             float* __restrict__ out) {
    int idx = blockIdx.x * blockDim.x + threadIdx.x;
    if (idx >= NB * NR * NHW) return;

    float l0 = (rw[0] + gr[0]) / 10.0f;
    float l1 = (rw[1] + gr[1]) / 10.0f;
    float mm = fmaxf(l0, l1);
    float e0 = expf(l0 - mm), e1 = expf(l1 - mm);
    float inv = 1.0f / (e0 + e1);
    float b0 = e0 * inv, b1 = e1 * inv;

    int b = idx / (NR * NHW);
    int rem = idx - b * (NR * NHW);
    int r = rem / NHW;
    int hw = rem - r * NHW;
    float off = c_offs[r];
    float t = off / PI_F;
    float pr = -0.5f * t * t - LOG_SIGMA - HALF_LOG2PI;

    float a = b1 * d_attn1[(b * NR + r) * NHW + hw];
    bool even = ((r & 1) == 0);
    if (even) a += b0 * d_attn0[(b * 4 + (r >> 1)) * NHW + hw];
    a += pr;
    out[OFF_ATTN + idx] = a;

    float zv[4];
#pragma unroll
    for (int l = 0; l < 4; ++l) {
        float z = b1 * d_z1[((b * 4 + l) * NR + r) * NHW + hw];
        if (even) z += b0 * d_z0[((b * 4 + l) * 4 + (r >> 1)) * NHW + hw];
        zv[l] = z;
        out[OFF_Z + ((b * 4 + l) * NR + r) * NHW + hw] = z;
    }
    out[OFF_TH + ((b * 2 + 0) * NR + r) * NHW + hw] = zv[0] + off;
    out[OFF_TH + ((b * 2 + 1) * NR + r) * NHW + hw] = zv[1];

    if (idx < 8) {
        float o2 = c_offs[idx];
        float t2 = o2 / PI_F;
        out[OFF_PR + idx] = -0.5f * t2 * t2 - LOG_SIGMA - HALF_LOG2PI;
        out[OFF_OFF + idx] = o2;
    }
}

// ============================================================
// K5: per-batch softmax stats (max / sumexp, two distributions)
// ============================================================
__global__ void stats_kern(const float* __restrict__ out,
                           const float* __restrict__ g) {
    __shared__ float sm[256];
    int b = blockIdx.x, tid = threadIdx.x;
    const float* a = out + OFF_ATTN + b * (NR * NHW);
    const float* gb = g + b * (NR * NHW);

    float m1 = -1e30f, m2 = -1e30f;
    for (int i = tid; i < NR * NHW; i += 256) {
        float v = a[i];
        m1 = fmaxf(m1, v);
        m2 = fmaxf(m2, v + gb[i]);
    }
    sm[tid] = m1; __syncthreads();
    for (int s = 128; s > 0; s >>= 1) {
        if (tid < s) sm[tid] = fmaxf(sm[tid], sm[tid + s]);
        __syncthreads();
    }
    m1 = sm[0]; __syncthreads();
    sm[tid] = m2; __syncthreads();
    for (int s = 128; s > 0; s >>= 1) {
        if (tid < s) sm[tid] = fmaxf(sm[tid], sm[tid + s]);
        __syncthreads();
    }
    m2 = sm[0]; __syncthreads();

    float s1 = 0.0f, s2 = 0.0f;
    for (int i = tid; i < NR * NHW; i += 256) {
        float v = a[i];
        s1 += expf(v - m1);
        s2 += expf(v + gb[i] - m2);
    }
    sm[tid] = s1; __syncthreads();
    for (int s = 128; s > 0; s >>= 1) {
        if (tid < s) sm[tid] += sm[tid + s];
        __syncthreads();
    }
    s1 = sm[0]; __syncthreads();
    sm[tid] = s2; __syncthreads();
    for (int s = 128; s > 0; s >>= 1) {
        if (tid < s) sm[tid] += sm[tid + s];
        __syncthreads();
    }
    s2 = sm[0];

    if (tid == 0) {
        d_stats[b * 4 + 0] = m1;
        d_stats[b * 4 + 1] = s1;
        d_stats[b * 4 + 2] = m2;
        d_stats[b * 4 + 3] = s2;
    }
}

// ============================================================
// K6: q_t_r (log_softmax) + a_sampled (gumbel softmax)
// ============================================================
__global__ void final_kern(const float* __restrict__ g,
                           float* __restrict__ out) {
    int idx = blockIdx.x * blockDim.x + threadIdx.x;
    if (idx >= NB * NR * NHW) return;
    int b = idx / (NR * NHW);
    float v = out[OFF_ATTN + idx];
    out[OFF_Q + idx] = (v - d_stats[b * 4 + 0]) - logf(d_stats[b * 4 + 1]);
    out[OFF_A + idx] =
        expf(v + g[idx] - d_stats[b * 4 + 2]) / d_stats[b * 4 + 3];
}

// ============================================================
extern "C" void kernel_launch(void* const* d_in, const int* in_sizes, int n_in,
                              void* d_out, int out_size) {
    const float* x   = (const float*)d_in[0];
    const float* ksw = (const float*)d_in[1];
    const float* rdw = (const float*)d_in[2];
    const float* w17 = (const float*)d_in[3];
    const float* b17 = (const float*)d_in[4];
    const float* w33 = (const float*)d_in[5];
    const float* b33 = (const float*)d_in[6];
    const float* w2  = (const float*)d_in[7];
    const float* b2  = (const float*)d_in[8];
    const float* wa  = (const float*)d_in[9];
    const float* ba  = (const float*)d_in[10];
    const float* wz  = (const float*)d_in[11];
    const float* bz  = (const float*)d_in[12];
    const float* gk  = (const float*)d_in[13];
    const float* gr  = (const float*)d_in[14];
    const float* ga  = (const float*)d_in[15];
    float* out = (float*)d_out;

    // dynamic smem sizes:
    //   K=33: xs 80*82*4 = 26240 B + ws2 8*1089*8 = 69696 B -> 95936 B
    //   K=17: xs 64*66*4 = 16896 B + ws2 8*289*8  = 18496 B -> 35392 B
    const int SM33 = 80 * 82 * 4 + 8 * 1089 * 8;
    const int SM17 = 64 * 66 * 4 + 8 * 289 * 8;
    cudaFuncSetAttribute((const void*)conv_group<33, 8, false>,
                         cudaFuncAttributeMaxDynamicSharedMemorySize, SM33);

    rotate_kern<17><<<(NR * NO * 289 + 255) / 256, 256>>>(w17);
    rotate_kern<33><<<(NR * NO * 1089 + 255) / 256, 256>>>(w33);

    conv_group<17, 0, true ><<<dim3(16, 64), 288, SM17>>>(x, b17, ksw, gk);
    conv_group<33, 8, false><<<dim3(16, 64), 288, SM33>>>(x, b33, ksw, gk);

    gemm_attnz<1><<<dim3(48, 64), 256>>>(w2 + 16384, b2 + 128, wa + 128,
                                         ba + 1, wz + 512, bz + 4);
    gemm_attnz<0><<<dim3(48, 32), 256>>>(w2, b2, wa, ba, wz, bz);

    combine_kern<<<(NB * NR * NHW + 255) / 256, 256>>>(rdw, gr, out);
    stats_kern<<<NB, 256>>>(out, ga);
    final_kern<<<(NB * NR * NHW + 255) / 256, 256>>>(ga, out);
}

// round 5
// speedup vs baseline: 1.1957x; 1.0805x over previous
#include <cuda_runtime.h>
#include <math.h>

#define NB 8
#define NO 128
#define NR 8
#define NH 48
#define NHW 2304
#define NX 64

// ---- output layout (concatenated flattened outputs, float32) ----
#define OFF_ATTN 0
#define OFF_Q    147456
#define OFF_PR   294912
#define OFF_A    294920
#define OFF_OFF  442376
#define OFF_TH   442384
#define OFF_Z    737296

typedef unsigned long long ull;

// ---- device scratch (static, no runtime allocation) ----
__device__ float d_rot17[NR * NO * 17 * 17];
__device__ float d_rot33[NR * NO * 33 * 33];
__device__ float d_xout[NB * NO * NR * NHW];     // [b][c][r][hw]
__device__ float d_attn1[NB * NR * NHW];
__device__ float d_attn0[NB * 4 * NHW];
__device__ float d_z1[NB * 4 * NR * NHW];        // [b][l][r][hw]
__device__ float d_z0[NB * 4 * 4 * NHW];
__device__ float d_stats[NB * 4];                // m1, s1, m2, s2

__constant__ float c_offs[8] = {
    0.0f, 0.7853981633974483f, 1.5707963267948966f, 2.356194490192345f,
    3.141592653589793f, -2.356194490192345f, -1.5707963267948966f,
    -0.7853981633974483f};

#define LOG_SIGMA   1.1447298858494002f   // log(pi), f32
#define HALF_LOG2PI 0.9189385332046727f   // 0.5*log(2*pi), f32
#define PI_F        3.14159265358979323846f

// packed f32x2 helpers (FFMA2 is PTX-only; ptxas never auto-fuses)
#define FFMA2(acc, a, b) \
    asm("fma.rn.f32x2 %0, %1, %2, %0;" : "+l"(acc) : "l"(a), "l"(b))
#define PACK2(dst, lo, hi) \
    asm("mov.b64 %0, {%1, %2};" : "=l"(dst) : "f"(lo), "f"(hi))
#define UNPACK2(lo, hi, src) \
    asm("mov.b64 {%0, %1}, %2;" : "=f"(lo), "=f"(hi) : "l"(src))

// ============================================================
// K1: rotate kernels (bilinear grid_sample semantics, zero pad)
// ============================================================
template <int K>
__global__ void rotate_kern(const float* __restrict__ w) {
    constexpr int KK = K * K;
    float* out = (K == 17) ? d_rot17 : d_rot33;
    int idx = blockIdx.x * blockDim.x + threadIdx.x;
    if (idx >= NR * NO * KK) return;
    int j = idx % K;
    int t = idx / K;
    int i = t % K; t /= K;
    int o = t % NO;
    int r = t / NO;

    float theta = 0.7853981633974483f * (float)r;  // (2*pi/8)*r in f32
    float c = cosf(theta), s = sinf(theta);
    float gy = (2.0f * (float)i + 1.0f) / (float)K - 1.0f;
    float gx = (2.0f * (float)j + 1.0f) / (float)K - 1.0f;
    float sx = c * gx - s * gy;
    float sy = s * gx + c * gy;
    float fx = ((sx + 1.0f) * (float)K - 1.0f) * 0.5f;
    float fy = ((sy + 1.0f) * (float)K - 1.0f) * 0.5f;
    int x0 = (int)floorf(fx);
    int y0 = (int)floorf(fy);
    float wx1 = fx - (float)x0;
    float wy1 = fy - (float)y0;
    const float* wo = w + o * KK;

    auto g = [&](int y, int x) -> float {
        if (y < 0 || y >= K || x < 0 || x >= K) return 0.0f;
        return wo[y * K + x];
    };
    float v = g(y0, x0) * (1.0f - wy1) * (1.0f - wx1)
            + g(y0, x0 + 1) * (1.0f - wy1) * wx1
            + g(y0 + 1, x0) * wy1 * (1.0f - wx1)
            + g(y0 + 1, x0 + 1) * wy1 * wx1;
    out[idx] = v;
}

// ============================================================
// K2: group conv + bias + lrelu + alpha-combine into d_xout
//   block: fixed (b, r), 4 output channels (2 FFMA2 channel-pairs),
//   full 48x48 spatial; thread: 8 rows x 1 col.
//   kx-outer / ky-inner with an 8-row sliding window of (x,x)
//   pairs in registers: per (ky,kx) only 1 LDS.32 + 1 pack +
//   2 LDS.64 (weight pair broadcast) + 16 FFMA2.
// ============================================================
template <int K, int PAD, bool FIRST>
__global__ __launch_bounds__(288, 3) void conv_group(
    const float* __restrict__ x, const float* __restrict__ bias,
    const float* __restrict__ kw, const float* __restrict__ gk) {
    constexpr int XD = NX + 2 * PAD;
    constexpr int XS = XD + 2;          // even stride: warp row-groups disjoint banks
    constexpr int KK = K * K;
    const float* rot = (K == 17) ? d_rot17 : d_rot33;

    extern __shared__ float smem_dyn[];
    float* xs = smem_dyn;                                 // XD*XS floats
    ull* ws2 = (ull*)(smem_dyn + XD * XS);                // [kk][op], 2*KK pairs

    int tid = threadIdx.x;
    int b = blockIdx.y >> 3;
    int r = blockIdx.y & 7;
    int o0 = blockIdx.x * 4;

    const float* xb = x + b * NX * NX;
    for (int idx = tid; idx < XD * XD; idx += 288) {
        int row = idx / XD, col = idx - row * XD;
        int gr = row - PAD, gc = col - PAD;
        float v = 0.0f;
        if (gr >= 0 && gr < NX && gc >= 0 && gc < NX) v = xb[gr * NX + gc];
        xs[row * XS + col] = v;
    }
    // stage weights as channel-pairs: ws2[kk*2+op] = (w[o0+2op], w[o0+2op+1])
    const float* rbase = rot + (r * NO + o0) * KK;
    for (int idx = tid; idx < 2 * KK; idx += 288) {
        int kk = idx >> 1, op = idx & 1;
        float lo = rbase[(2 * op) * KK + kk];
        float hi = rbase[(2 * op + 1) * KK + kk];
        ull p;
        PACK2(p, lo, hi);
        ws2[idx] = p;
    }
    __syncthreads();

    int tc = tid % 48;
    int tr0 = (tid / 48) * 8;

    ull acc[2][8];
#pragma unroll
    for (int op = 0; op < 2; ++op)
#pragma unroll
        for (int dr = 0; dr < 8; ++dr) acc[op][dr] = 0ull;

#pragma unroll 1
    for (int kx = 0; kx < K; ++kx) {
        const float* xcol = xs + tr0 * XS + tc + kx;
        // preload 7-row window as (x,x) pairs
        ull win[8];
#pragma unroll
        for (int i = 0; i < 7; ++i) {
            float v = xcol[i * XS];
            PACK2(win[i], v, v);
        }
        const ull* wp = ws2 + kx * 2;
#pragma unroll
        for (int ky = 0; ky < K; ++ky) {
            {
                float v = xcol[(ky + 7) * XS];
                PACK2(win[(ky + 7) & 7], v, v);
            }
            ull w0 = wp[ky * (2 * K) + 0];
            ull w1 = wp[ky * (2 * K) + 1];
#pragma unroll
            for (int dr = 0; dr < 8; ++dr) {
                ull xv = win[(ky + dr) & 7];
                FFMA2(acc[0][dr], w0, xv);
                FFMA2(acc[1][dr], w1, xv);
            }
        }
    }

    // gumbel-softmax alpha over kernel sizes
    float l0 = (kw[0] + gk[0]) / 10.0f;
    float l1 = (kw[1] + gk[1]) / 10.0f;
    float mm = fmaxf(l0, l1);
    float e0 = expf(l0 - mm), e1 = expf(l1 - mm);
    float alpha = (FIRST ? e0 : e1) / (e0 + e1);

#pragma unroll
    for (int op = 0; op < 2; ++op) {
        float b0v = bias[o0 + 2 * op];
        float b1v = bias[o0 + 2 * op + 1];
        float* p0 = d_xout + (((b * NO + o0 + 2 * op) * NR + r) * NHW)
                    + tr0 * 48 + tc;
        float* p1 = p0 + NR * NHW;
#pragma unroll
        for (int dr = 0; dr < 8; ++dr) {
            float v0, v1;
            UNPACK2(v0, v1, acc[op][dr]);
            v0 += b0v;
            v1 += b1v;
            v0 = (v0 >= 0.0f) ? v0 : 0.01f * v0;
            v1 = (v1 >= 0.0f) ? v1 : 0.01f * v1;
            v0 *= alpha;
            v1 *= alpha;
            if (FIRST) {
                p0[dr * 48] = v0;
                p1[dr * 48] = v1;
            } else {
                p0[dr * 48] += v0;
                p1[dr * 48] += v1;
            }
        }
    }
}

// ============================================================
// K3: fused conv2(128x128) + lrelu + conva(1) + convz(4) heads
//   block: fixed (b, r, spatial row h); 256 thr = 16 o-grp x 16 n-grp
//   main GEMM loop uses FFMA2 over channel pairs (o, o+16)
// ============================================================
template <int BRANCH>
__global__ __launch_bounds__(256) void gemm_attnz(
    const float* __restrict__ w2, const float* __restrict__ b2,
    const float* __restrict__ wa, const float* __restrict__ ba,
    const float* __restrict__ wz, const float* __restrict__ bz) {
    constexpr int RCOUNT = BRANCH ? 8 : 4;
    constexpr int RSTEP = BRANCH ? 1 : 2;
    float* attn_out = BRANCH ? d_attn1 : d_attn0;
    float* z_out = BRANCH ? d_z1 : d_z0;

    __shared__ ull ws2[32 * 64];     // [cc][p][to]: pair (o=32p+to, o=32p+16+to)
    __shared__ float xt[128 * 48];   // [c][n]

    int tid = threadIdx.x;
    int to = tid & 15;
    int tn = tid >> 4;
    int h = blockIdx.x;
    int brs = blockIdx.y;
    int b = brs / RCOUNT;
    int rsub = brs - b * RCOUNT;
    int r = rsub * RSTEP;

    const float* xb = d_xout + ((b * NO) * NR + r) * NHW + h * 48;
    for (int idx = tid; idx < 6144; idx += 256) {
        int c = idx / 48, n = idx - c * 48;
        xt[idx] = xb[c * (NR * NHW) + n];
    }

    ull acc2[4][3];
#pragma unroll
    for (int p = 0; p < 4; ++p)
#pragma unroll
        for (int j = 0; j < 3; ++j) acc2[p][j] = 0ull;

    for (int kc = 0; kc < 4; ++kc) {
        __syncthreads();
        for (int idx = tid; idx < 2048; idx += 256) {
            int cc = idx >> 6, rest = idx & 63;
            int p = rest >> 4, t = rest & 15;
            float lo = w2[(32 * p + t) * 128 + kc * 32 + cc];
            float hi = w2[(32 * p + 16 + t) * 128 + kc * 32 + cc];
            ull pr;
            PACK2(pr, lo, hi);
            ws2[idx] = pr;
        }
        __syncthreads();
#pragma unroll 4
        for (int cc = 0; cc < 32; ++cc) {
            int k = kc * 32 + cc;
            ull xp[3];
#pragma unroll
            for (int j = 0; j < 3; ++j) {
                float v = xt[k * 48 + tn * 3 + j];
                PACK2(xp[j], v, v);
            }
#pragma unroll
            for (int p = 0; p < 4; ++p) {
                ull wv = ws2[cc * 64 + p * 16 + to];
                FFMA2(acc2[p][0], wv, xp[0]);
                FFMA2(acc2[p][1], wv, xp[1]);
                FFMA2(acc2[p][2], wv, xp[2]);
            }
        }
    }

    // epilogue: h = lrelu(acc + b2[o]); heads reduce over o
    float pa[3] = {0.f, 0.f, 0.f};
    float pz[4][3];
#pragma unroll
    for (int l = 0; l < 4; ++l)
#pragma unroll
        for (int j = 0; j < 3; ++j) pz[l][j] = 0.0f;

#pragma unroll
    for (int p = 0; p < 4; ++p) {
#pragma unroll
        for (int half = 0; half < 2; ++half) {
            int o = 32 * p + 16 * half + to;
            float bb = b2[o];
            float wav = wa[o];
            float w0 = wz[o], w1 = wz[128 + o], w2v = wz[256 + o],
                  w3 = wz[384 + o];
#pragma unroll
            for (int j = 0; j < 3; ++j) {
                float v0, v1;
                UNPACK2(v0, v1, acc2[p][j]);
                float hv = half ? v1 : v0;
                hv += bb;
                hv = (hv >= 0.0f) ? hv : 0.01f * hv;
                pa[j] = fmaf(wav, hv, pa[j]);
                pz[0][j] = fmaf(w0, hv, pz[0][j]);
                pz[1][j] = fmaf(w1, hv, pz[1][j]);
                pz[2][j] = fmaf(w2v, hv, pz[2][j]);
                pz[3][j] = fmaf(w3, hv, pz[3][j]);
            }
        }
    }

    // reduce across the 16 o-groups (lanes differing in bits 0..3)
#pragma unroll
    for (int m = 8; m >= 1; m >>= 1) {
#pragma unroll
        for (int j = 0; j < 3; ++j) {
            pa[j] += __shfl_xor_sync(0xffffffffu, pa[j], m);
#pragma unroll
            for (int l = 0; l < 4; ++l)
                pz[l][j] += __shfl_xor_sync(0xffffffffu, pz[l][j], m);
        }
    }

    if (to == 0) {
        int nbase = h * 48 + tn * 3;
#pragma unroll
        for (int j = 0; j < 3; ++j)
            attn_out[(b * RCOUNT + rsub) * NHW + nbase + j] = pa[j] + ba[0];
#pragma unroll
        for (int l = 0; l < 4; ++l)
#pragma unroll
            for (int j = 0; j < 3; ++j)
                z_out[((b * 4 + l) * RCOUNT + rsub) * NHW + nbase + j] =
                    pz[l][j] + bz[l];
    }
}

// ============================================================
// K4: scatter combine (betas) + p_r; writes attn, z, theta,
//     p_r, offsets directly into d_out
// ============================================================
__global__ void combine_kern(const float* __restrict__ rw,
                             const float* __restrict__ gr,
                             float* __restrict__ out) {
    int idx = blockIdx.x * blockDim.x + threadIdx.x;
    if (idx >= NB * NR * NHW) return;

    float l0 = (rw[0] + gr[0]) / 10.0f;
    float l1 = (rw[1] + gr[1]) / 10.0f;
    float mm = fmaxf(l0, l1);
    float e0 = expf(l0 - mm), e1 = expf(l1 - mm);
    float inv = 1.0f / (e0 + e1);
    float b0 = e0 * inv, b1 = e1 * inv;

    int b = idx / (NR * NHW);
    int rem = idx - b * (NR * NHW);
    int r = rem / NHW;
    int hw = rem - r * NHW;
    float off = c_offs[r];
    float t = off / PI_F;
    float pr = -0.5f * t * t - LOG_SIGMA - HALF_LOG2PI;

    float a = b1 * d_attn1[(b * NR + r) * NHW + hw];
    bool even = ((r & 1) == 0);
    if (even) a += b0 * d_attn0[(b * 4 + (r >> 1)) * NHW + hw];
    a += pr;
    out[OFF_ATTN + idx] = a;

    float zv[4];
#pragma unroll
    for (int l = 0; l < 4; ++l) {
        float z = b1 * d_z1[((b * 4 + l) * NR + r) * NHW + hw];
        if (even) z += b0 * d_z0[((b * 4 + l) * 4 + (r >> 1)) * NHW + hw];
        zv[l] = z;
        out[OFF_Z + ((b * 4 + l) * NR + r) * NHW + hw] = z;
    }
    out[OFF_TH + ((b * 2 + 0) * NR + r) * NHW + hw] = zv[0] + off;
    out[OFF_TH + ((b * 2 + 1) * NR + r) * NHW + hw] = zv[1];

    if (idx < 8) {
        float o2 = c_offs[idx];
        float t2 = o2 / PI_F;
        out[OFF_PR + idx] = -0.5f * t2 * t2 - LOG_SIGMA - HALF_LOG2PI;
        out[OFF_OFF + idx] = o2;
    }
}

// ============================================================
// K5: per-batch softmax stats (max / sumexp, two distributions)
// ============================================================
__global__ void stats_kern(const float* __restrict__ out,
                           const float* __restrict__ g) {
    __shared__ float sm[256];
    int b = blockIdx.x, tid = threadIdx.x;
    const float* a = out + OFF_ATTN + b * (NR * NHW);
    const float* gb = g + b * (NR * NHW);

    float m1 = -1e30f, m2 = -1e30f;
    for (int i = tid; i < NR * NHW; i += 256) {
        float v = a[i];
        m1 = fmaxf(m1, v);
        m2 = fmaxf(m2, v + gb[i]);
    }
    sm[tid] = m1; __syncthreads();
    for (int s = 128; s > 0; s >>= 1) {
        if (tid < s) sm[tid] = fmaxf(sm[tid], sm[tid + s]);
        __syncthreads();
    }
    m1 = sm[0]; __syncthreads();
    sm[tid] = m2; __syncthreads();
    for (int s = 128; s > 0; s >>= 1) {
        if (tid < s) sm[tid] = fmaxf(sm[tid], sm[tid + s]);
        __syncthreads();
    }
    m2 = sm[0]; __syncthreads();

    float s1 = 0.0f, s2 = 0.0f;
    for (int i = tid; i < NR * NHW; i += 256) {
        float v = a[i];
        s1 += expf(v - m1);
        s2 += expf(v + gb[i] - m2);
    }
    sm[tid] = s1; __syncthreads();
    for (int s = 128; s > 0; s >>= 1) {
        if (tid < s) sm[tid] += sm[tid + s];
        __syncthreads();
    }
    s1 = sm[0]; __syncthreads();
    sm[tid] = s2; __syncthreads();
    for (int s = 128; s > 0; s >>= 1) {
        if (tid < s) sm[tid] += sm[tid + s];
        __syncthreads();
    }
    s2 = sm[0];

    if (tid == 0) {
        d_stats[b * 4 + 0] = m1;
        d_stats[b * 4 + 1] = s1;
        d_stats[b * 4 + 2] = m2;
        d_stats[b * 4 + 3] = s2;
    }
}

// ============================================================
// K6: q_t_r (log_softmax) + a_sampled (gumbel softmax)
// ============================================================
__global__ void final_kern(const float* __restrict__ g,
                           float* __restrict__ out) {
    int idx = blockIdx.x * blockDim.x + threadIdx.x;
    if (idx >= NB * NR * NHW) return;
    int b = idx / (NR * NHW);
    float v = out[OFF_ATTN + idx];
    out[OFF_Q + idx] = (v - d_stats[b * 4 + 0]) - logf(d_stats[b * 4 + 1]);
    out[OFF_A + idx] =
        expf(v + g[idx] - d_stats[b * 4 + 2]) / d_stats[b * 4 + 3];
}

// ============================================================
extern "C" void kernel_launch(void* const* d_in, const int* in_sizes, int n_in,
                              void* d_out, int out_size) {
    const float* x   = (const float*)d_in[0];
    const float* ksw = (const float*)d_in[1];
    const float* rdw = (const float*)d_in[2];
    const float* w17 = (const float*)d_in[3];
    const float* b17 = (const float*)d_in[4];
    const float* w33 = (const float*)d_in[5];
    const float* b33 = (const float*)d_in[6];
    const float* w2  = (const float*)d_in[7];
    const float* b2  = (const float*)d_in[8];
    const float* wa  = (const float*)d_in[9];
    const float* ba  = (const float*)d_in[10];
    const float* wz  = (const float*)d_in[11];
    const float* bz  = (const float*)d_in[12];
    const float* gk  = (const float*)d_in[13];
    const float* gr  = (const float*)d_in[14];
    const float* ga  = (const float*)d_in[15];
    float* out = (float*)d_out;

    // dynamic smem:
    //   K=33: xs 80*82*4 = 26240 B + ws2 2*1089*8 = 17424 B -> 43664 B
    //   K=17: xs 64*66*4 = 16896 B + ws2 2*289*8  =  4624 B -> 21520 B
    const int SM33 = 80 * 82 * 4 + 2 * 1089 * 8;
    const int SM17 = 64 * 66 * 4 + 2 * 289 * 8;

    rotate_kern<17><<<(NR * NO * 289 + 255) / 256, 256>>>(w17);
    rotate_kern<33><<<(NR * NO * 1089 + 255) / 256, 256>>>(w33);

    conv_group<17, 0, true ><<<dim3(32, 64), 288, SM17>>>(x, b17, ksw, gk);
    conv_group<33, 8, false><<<dim3(32, 64), 288, SM33>>>(x, b33, ksw, gk);

    gemm_attnz<1><<<dim3(48, 64), 256>>>(w2 + 16384, b2 + 128, wa + 128,
                                         ba + 1, wz + 512, bz + 4);
    gemm_attnz<0><<<dim3(48, 32), 256>>>(w2, b2, wa, ba, wz, bz);

    combine_kern<<<(NB * NR * NHW + 255) / 256, 256>>>(rdw, gr, out);
    stats_kern<<<NB, 256>>>(out, ga);
    final_kern<<<(NB * NR * NHW + 255) / 256, 256>>>(ga, out);
}

// round 6
// speedup vs baseline: 1.3270x; 1.1099x over previous
#include <cuda_runtime.h>
#include <math.h>

#define NB 8
#define NO 128
#define NR 8
#define NH 48
#define NHW 2304
#define NX 64

// ---- output layout (concatenated flattened outputs, float32) ----
#define OFF_ATTN 0
#define OFF_Q    147456
#define OFF_PR   294912
#define OFF_A    294920
#define OFF_OFF  442376
#define OFF_TH   442384
#define OFF_Z    737296

typedef unsigned long long ull;

// ---- device scratch (static, no runtime allocation) ----
__device__ float d_rot17[NR * NO * 17 * 17];
__device__ float d_rot33[NR * NO * 33 * 33];
__device__ float d_xout[NB * NO * NR * NHW];     // [b][c][r][hw]
__device__ float d_attn1[NB * NR * NHW];
__device__ float d_attn0[NB * 4 * NHW];
__device__ float d_z1[NB * 4 * NR * NHW];        // [b][l][r][hw]
__device__ float d_z0[NB * 4 * 4 * NHW];
__device__ float d_stats[NB * 4];                // m1, s1, m2, s2

__constant__ float c_offs[8] = {
    0.0f, 0.7853981633974483f, 1.5707963267948966f, 2.356194490192345f,
    3.141592653589793f, -2.356194490192345f, -1.5707963267948966f,
    -0.7853981633974483f};

#define LOG_SIGMA   1.1447298858494002f   // log(pi), f32
#define HALF_LOG2PI 0.9189385332046727f   // 0.5*log(2*pi), f32
#define PI_F        3.14159265358979323846f

// packed f32x2 helpers (FFMA2 is PTX-only; ptxas never auto-fuses)
#define FFMA2(acc, a, b) \
    asm("fma.rn.f32x2 %0, %1, %2, %0;" : "+l"(acc) : "l"(a), "l"(b))
#define PACK2(dst, lo, hi) \
    asm("mov.b64 %0, {%1, %2};" : "=l"(dst) : "f"(lo), "f"(hi))
#define UNPACK2(lo, hi, src) \
    asm("mov.b64 {%0, %1}, %2;" : "=f"(lo), "=f"(hi) : "l"(src))

// tf32 tensor-core helpers
__device__ __forceinline__ unsigned f2tf(float v) {
    unsigned r;
    asm("cvt.rn.tf32.f32 %0, %1;" : "=r"(r) : "f"(v));
    return r;
}
#define MMA_TF32(c, a0, a1, a2, a3, b0, b1)                                 \
    asm volatile(                                                           \
        "mma.sync.aligned.m16n8k8.row.col.f32.tf32.tf32.f32 "               \
        "{%0,%1,%2,%3}, {%4,%5,%6,%7}, {%8,%9}, {%0,%1,%2,%3};"             \
        : "+f"((c)[0]), "+f"((c)[1]), "+f"((c)[2]), "+f"((c)[3])            \
        : "r"(a0), "r"(a1), "r"(a2), "r"(a3), "r"(b0), "r"(b1))

// ============================================================
// K1: rotate kernels (bilinear grid_sample semantics, zero pad)
// ============================================================
template <int K>
__global__ void rotate_kern(const float* __restrict__ w) {
    constexpr int KK = K * K;
    float* out = (K == 17) ? d_rot17 : d_rot33;
    int idx = blockIdx.x * blockDim.x + threadIdx.x;
    if (idx >= NR * NO * KK) return;
    int j = idx % K;
    int t = idx / K;
    int i = t % K; t /= K;
    int o = t % NO;
    int r = t / NO;

    float theta = 0.7853981633974483f * (float)r;  // (2*pi/8)*r in f32
    float c = cosf(theta), s = sinf(theta);
    float gy = (2.0f * (float)i + 1.0f) / (float)K - 1.0f;
    float gx = (2.0f * (float)j + 1.0f) / (float)K - 1.0f;
    float sx = c * gx - s * gy;
    float sy = s * gx + c * gy;
    float fx = ((sx + 1.0f) * (float)K - 1.0f) * 0.5f;
    float fy = ((sy + 1.0f) * (float)K - 1.0f) * 0.5f;
    int x0 = (int)floorf(fx);
    int y0 = (int)floorf(fy);
    float wx1 = fx - (float)x0;
    float wy1 = fy - (float)y0;
    const float* wo = w + o * KK;

    auto g = [&](int y, int x) -> float {
        if (y < 0 || y >= K || x < 0 || x >= K) return 0.0f;
        return wo[y * K + x];
    };
    float v = g(y0, x0) * (1.0f - wy1) * (1.0f - wx1)
            + g(y0, x0 + 1) * (1.0f - wy1) * wx1
            + g(y0 + 1, x0) * wy1 * (1.0f - wx1)
            + g(y0 + 1, x0 + 1) * wy1 * wx1;
    out[idx] = v;
}

// ============================================================
// K2: group conv via tf32 mma.sync implicit-GEMM
//   per block: one (b, r), M=128 o x N=192 spatial (4 rows x 48)
//   K-loop: ky outer (restage weight row), kx chunks of 8 (padded)
//   warp (of 16): M16 x N96 -> 12 m16n8k8 mma per chunk
//   B operand = im2col patches read directly from x tile in smem
// ============================================================
template <int K, int PAD, int KXP, int WSS, bool FIRST>
__global__ __launch_bounds__(512) void conv_mma(
    const float* __restrict__ x, const float* __restrict__ bias,
    const float* __restrict__ kw, const float* __restrict__ gk) {
    constexpr int XROWS = K + 3;
    constexpr int XCOLS = 48 + KXP;
    constexpr int NCH = KXP / 8;
    const float* rot = (K == 17) ? d_rot17 : d_rot33;

    __shared__ unsigned xsT[XROWS * XCOLS];   // tf32 x tile
    __shared__ unsigned ws[128 * WSS];        // tf32 weights, one ky row

    int tid = threadIdx.x;
    int lane = tid & 31, wid = tid >> 5;
    int gid = lane >> 2, tig = lane & 3;
    int wm = wid & 7;      // o tile: [16*wm, 16*wm+16)
    int wn = wid >> 3;     // y half: rows 2*wn, 2*wn+1 of the 4-row tile
    int y0 = blockIdx.x * 4;
    int b = blockIdx.y >> 3, r = blockIdx.y & 7;

    // stage x tile as tf32 (zero-padded boundaries + kx padding region)
    const float* xb = x + b * NX * NX;
    for (int idx = tid; idx < XROWS * XCOLS; idx += 512) {
        int row = idx / XCOLS, col = idx - row * XCOLS;
        int gr = y0 + row - PAD, gc = col - PAD;
        float v = (gr >= 0 && gr < NX && gc >= 0 && gc < NX)
                      ? xb[gr * NX + gc] : 0.0f;
        xsT[idx] = f2tf(v);
    }

    float acc[12][4];
#pragma unroll
    for (int j = 0; j < 12; ++j)
#pragma unroll
        for (int e = 0; e < 4; ++e) acc[j][e] = 0.0f;

    const float* rbase = rot + (r * NO) * (K * K);

#pragma unroll 1
    for (int ky = 0; ky < K; ++ky) {
        __syncthreads();
        // stage this ky's weight row for all 128 o, kx padded to KXP
        for (int idx = tid; idx < 128 * KXP; idx += 512) {
            int o = idx / KXP, kx = idx - o * KXP;
            float v = (kx < K) ? rbase[o * (K * K) + ky * K + kx] : 0.0f;
            ws[o * WSS + kx] = f2tf(v);
        }
        __syncthreads();

#pragma unroll
        for (int kc = 0; kc < NCH; ++kc) {
            int kx0 = kc * 8;
            const unsigned* ap = ws + (16 * wm + gid) * WSS + kx0 + tig;
            unsigned a0 = ap[0];
            unsigned a1 = ap[8 * WSS];
            unsigned a2 = ap[4];
            unsigned a3 = ap[8 * WSS + 4];
#pragma unroll
            for (int j = 0; j < 12; ++j) {
                int yloc = 2 * wn + (j / 6);
                const unsigned* bp = xsT + (yloc + ky) * XCOLS
                                     + (j % 6) * 8 + gid + kx0 + tig;
                unsigned b0 = bp[0];
                unsigned b1 = bp[4];
                MMA_TF32(acc[j], a0, a1, a2, a3, b0, b1);
            }
        }
    }

    // gumbel-softmax alpha over kernel sizes
    float l0 = (kw[0] + gk[0]) / 10.0f;
    float l1 = (kw[1] + gk[1]) / 10.0f;
    float mm = fmaxf(l0, l1);
    float e0 = expf(l0 - mm), e1 = expf(l1 - mm);
    float alpha = (FIRST ? e0 : e1) / (e0 + e1);

    int o_lo = 16 * wm + gid;
    int o_hi = o_lo + 8;
    float blo = bias[o_lo], bhi = bias[o_hi];

#pragma unroll
    for (int j = 0; j < 12; ++j) {
        int y = y0 + 2 * wn + (j / 6);
        int xc = (j % 6) * 8 + 2 * tig;
#pragma unroll
        for (int half = 0; half < 2; ++half) {
            int o = half ? o_hi : o_lo;
            float bb = half ? bhi : blo;
            float v0 = acc[j][2 * half + 0] + bb;
            float v1 = acc[j][2 * half + 1] + bb;
            v0 = (v0 >= 0.0f) ? v0 : 0.01f * v0;
            v1 = (v1 >= 0.0f) ? v1 : 0.01f * v1;
            v0 *= alpha;
            v1 *= alpha;
            float2* p = (float2*)(d_xout + (((b * NO + o) * NR + r) * NHW)
                                  + y * 48 + xc);
            if (FIRST) {
                *p = make_float2(v0, v1);
            } else {
                float2 old = *p;
                *p = make_float2(old.x + v0, old.y + v1);
            }
        }
    }
}

// ============================================================
// K3: fused conv2(128x128) + lrelu + conva(1) + convz(4) heads
//   block: fixed (b, r, spatial row h); 256 thr = 16 o-grp x 16 n-grp
//   main GEMM loop uses FFMA2 over channel pairs (o, o+16)
// ============================================================
template <int BRANCH>
__global__ __launch_bounds__(256) void gemm_attnz(
    const float* __restrict__ w2, const float* __restrict__ b2,
    const float* __restrict__ wa, const float* __restrict__ ba,
    const float* __restrict__ wz, const float* __restrict__ bz) {
    constexpr int RCOUNT = BRANCH ? 8 : 4;
    constexpr int RSTEP = BRANCH ? 1 : 2;
    float* attn_out = BRANCH ? d_attn1 : d_attn0;
    float* z_out = BRANCH ? d_z1 : d_z0;

    __shared__ ull ws2[32 * 64];     // [cc][p][to]: pair (o=32p+to, o=32p+16+to)
    __shared__ float xt[128 * 48];   // [c][n]

    int tid = threadIdx.x;
    int to = tid & 15;
    int tn = tid >> 4;
    int h = blockIdx.x;
    int brs = blockIdx.y;
    int b = brs / RCOUNT;
    int rsub = brs - b * RCOUNT;
    int r = rsub * RSTEP;

    const float* xb = d_xout + ((b * NO) * NR + r) * NHW + h * 48;
    for (int idx = tid; idx < 6144; idx += 256) {
        int c = idx / 48, n = idx - c * 48;
        xt[idx] = xb[c * (NR * NHW) + n];
    }

    ull acc2[4][3];
#pragma unroll
    for (int p = 0; p < 4; ++p)
#pragma unroll
        for (int j = 0; j < 3; ++j) acc2[p][j] = 0ull;

    for (int kc = 0; kc < 4; ++kc) {
        __syncthreads();
        for (int idx = tid; idx < 2048; idx += 256) {
            int cc = idx >> 6, rest = idx & 63;
            int p = rest >> 4, t = rest & 15;
            float lo = w2[(32 * p + t) * 128 + kc * 32 + cc];
            float hi = w2[(32 * p + 16 + t) * 128 + kc * 32 + cc];
            ull pr;
            PACK2(pr, lo, hi);
            ws2[idx] = pr;
        }
        __syncthreads();
#pragma unroll 4
        for (int cc = 0; cc < 32; ++cc) {
            int k = kc * 32 + cc;
            ull xp[3];
#pragma unroll
            for (int j = 0; j < 3; ++j) {
                float v = xt[k * 48 + tn * 3 + j];
                PACK2(xp[j], v, v);
            }
#pragma unroll
            for (int p = 0; p < 4; ++p) {
                ull wv = ws2[cc * 64 + p * 16 + to];
                FFMA2(acc2[p][0], wv, xp[0]);
                FFMA2(acc2[p][1], wv, xp[1]);
                FFMA2(acc2[p][2], wv, xp[2]);
            }
        }
    }

    // epilogue: h = lrelu(acc + b2[o]); heads reduce over o
    float pa[3] = {0.f, 0.f, 0.f};
    float pz[4][3];
#pragma unroll
    for (int l = 0; l < 4; ++l)
#pragma unroll
        for (int j = 0; j < 3; ++j) pz[l][j] = 0.0f;

#pragma unroll
    for (int p = 0; p < 4; ++p) {
#pragma unroll
        for (int half = 0; half < 2; ++half) {
            int o = 32 * p + 16 * half + to;
            float bb = b2[o];
            float wav = wa[o];
            float w0 = wz[o], w1 = wz[128 + o], w2v = wz[256 + o],
                  w3 = wz[384 + o];
#pragma unroll
            for (int j = 0; j < 3; ++j) {
                float v0, v1;
                UNPACK2(v0, v1, acc2[p][j]);
                float hv = half ? v1 : v0;
                hv += bb;
                hv = (hv >= 0.0f) ? hv : 0.01f * hv;
                pa[j] = fmaf(wav, hv, pa[j]);
                pz[0][j] = fmaf(w0, hv, pz[0][j]);
                pz[1][j] = fmaf(w1, hv, pz[1][j]);
                pz[2][j] = fmaf(w2v, hv, pz[2][j]);
                pz[3][j] = fmaf(w3, hv, pz[3][j]);
            }
        }
    }

    // reduce across the 16 o-groups (lanes differing in bits 0..3)
#pragma unroll
    for (int m = 8; m >= 1; m >>= 1) {
#pragma unroll
        for (int j = 0; j < 3; ++j) {
            pa[j] += __shfl_xor_sync(0xffffffffu, pa[j], m);
#pragma unroll
            for (int l = 0; l < 4; ++l)
                pz[l][j] += __shfl_xor_sync(0xffffffffu, pz[l][j], m);
        }
    }

    if (to == 0) {
        int nbase = h * 48 + tn * 3;
#pragma unroll
        for (int j = 0; j < 3; ++j)
            attn_out[(b * RCOUNT + rsub) * NHW + nbase + j] = pa[j] + ba[0];
#pragma unroll
        for (int l = 0; l < 4; ++l)
#pragma unroll
            for (int j = 0; j < 3; ++j)
                z_out[((b * 4 + l) * RCOUNT + rsub) * NHW + nbase + j] =
                    pz[l][j] + bz[l];
    }
}

// ============================================================
// K4: scatter combine (betas) + p_r; writes attn, z, theta,
//     p_r, offsets directly into d_out
// ============================================================
__global__ void combine_kern(const float* __restrict__ rw,
                             const float* __restrict__ gr,
                             float* __restrict__ out) {
    int idx = blockIdx.x * blockDim.x + threadIdx.x;
    if (idx >= NB * NR * NHW) return;

    float l0 = (rw[0] + gr[0]) / 10.0f;
    float l1 = (rw[1] + gr[1]) / 10.0f;
    float mm = fmaxf(l0, l1);
    float e0 = expf(l0 - mm), e1 = expf(l1 - mm);
    float inv = 1.0f / (e0 + e1);
    float b0 = e0 * inv, b1 = e1 * inv;

    int b = idx / (NR * NHW);
    int rem = idx - b * (NR * NHW);
    int r = rem / NHW;
    int hw = rem - r * NHW;
    float off = c_offs[r];
    float t = off / PI_F;
    float pr = -0.5f * t * t - LOG_SIGMA - HALF_LOG2PI;

    float a = b1 * d_attn1[(b * NR + r) * NHW + hw];
    bool even = ((r & 1) == 0);
    if (even) a += b0 * d_attn0[(b * 4 + (r >> 1)) * NHW + hw];
    a += pr;
    out[OFF_ATTN + idx] = a;

    float zv[4];
#pragma unroll
    for (int l = 0; l < 4; ++l) {
        float z = b1 * d_z1[((b * 4 + l) * NR + r) * NHW + hw];
        if (even) z += b0 * d_z0[((b * 4 + l) * 4 + (r >> 1)) * NHW + hw];
        zv[l] = z;
        out[OFF_Z + ((b * 4 + l) * NR + r) * NHW + hw] = z;
    }
    out[OFF_TH + ((b * 2 + 0) * NR + r) * NHW + hw] = zv[0] + off;
    out[OFF_TH + ((b * 2 + 1) * NR + r) * NHW + hw] = zv[1];

    if (idx < 8) {
        float o2 = c_offs[idx];
        float t2 = o2 / PI_F;
        out[OFF_PR + idx] = -0.5f * t2 * t2 - LOG_SIGMA - HALF_LOG2PI;
        out[OFF_OFF + idx] = o2;
    }
}

// ============================================================
// K5: per-batch softmax stats (max / sumexp, two distributions)
// ============================================================
__global__ void stats_kern(const float* __restrict__ out,
                           const float* __restrict__ g) {
    __shared__ float sm[256];
    int b = blockIdx.x, tid = threadIdx.x;
    const float* a = out + OFF_ATTN + b * (NR * NHW);
    const float* gb = g + b * (NR * NHW);

    float m1 = -1e30f, m2 = -1e30f;
    for (int i = tid; i < NR * NHW; i += 256) {
        float v = a[i];
        m1 = fmaxf(m1, v);
        m2 = fmaxf(m2, v + gb[i]);
    }
    sm[tid] = m1; __syncthreads();
    for (int s = 128; s > 0; s >>= 1) {
        if (tid < s) sm[tid] = fmaxf(sm[tid], sm[tid + s]);
        __syncthreads();
    }
    m1 = sm[0]; __syncthreads();
    sm[tid] = m2; __syncthreads();
    for (int s = 128; s > 0; s >>= 1) {
        if (tid < s) sm[tid] = fmaxf(sm[tid], sm[tid + s]);
        __syncthreads();
    }
    m2 = sm[0]; __syncthreads();

    float s1 = 0.0f, s2 = 0.0f;
    for (int i = tid; i < NR * NHW; i += 256) {
        float v = a[i];
        s1 += expf(v - m1);
        s2 += expf(v + gb[i] - m2);
    }
    sm[tid] = s1; __syncthreads();
    for (int s = 128; s > 0; s >>= 1) {
        if (tid < s) sm[tid] += sm[tid + s];
        __syncthreads();
    }
    s1 = sm[0]; __syncthreads();
    sm[tid] = s2; __syncthreads();
    for (int s = 128; s > 0; s >>= 1) {
        if (tid < s) sm[tid] += sm[tid + s];
        __syncthreads();
    }
    s2 = sm[0];

    if (tid == 0) {
        d_stats[b * 4 + 0] = m1;
        d_stats[b * 4 + 1] = s1;
        d_stats[b * 4 + 2] = m2;
        d_stats[b * 4 + 3] = s2;
    }
}

// ============================================================
// K6: q_t_r (log_softmax) + a_sampled (gumbel softmax)
// ============================================================
__global__ void final_kern(const float* __restrict__ g,
                           float* __restrict__ out) {
    int idx = blockIdx.x * blockDim.x + threadIdx.x;
    if (idx >= NB * NR * NHW) return;
    int b = idx / (NR * NHW);
    float v = out[OFF_ATTN + idx];
    out[OFF_Q + idx] = (v - d_stats[b * 4 + 0]) - logf(d_stats[b * 4 + 1]);
    out[OFF_A + idx] =
        expf(v + g[idx] - d_stats[b * 4 + 2]) / d_stats[b * 4 + 3];
}

// ============================================================
extern "C" void kernel_launch(void* const* d_in, const int* in_sizes, int n_in,
                              void* d_out, int out_size) {
    const float* x   = (const float*)d_in[0];
    const float* ksw = (const float*)d_in[1];
    const float* rdw = (const float*)d_in[2];
    const float* w17 = (const float*)d_in[3];
    const float* b17 = (const float*)d_in[4];
    const float* w33 = (const float*)d_in[5];
    const float* b33 = (const float*)d_in[6];
    const float* w2  = (const float*)d_in[7];
    const float* b2  = (const float*)d_in[8];
    const float* wa  = (const float*)d_in[9];
    const float* ba  = (const float*)d_in[10];
    const float* wz  = (const float*)d_in[11];
    const float* bz  = (const float*)d_in[12];
    const float* gk  = (const float*)d_in[13];
    const float* gr  = (const float*)d_in[14];
    const float* ga  = (const float*)d_in[15];
    float* out = (float*)d_out;

    rotate_kern<17><<<(NR * NO * 289 + 255) / 256, 256>>>(w17);
    rotate_kern<33><<<(NR * NO * 1089 + 255) / 256, 256>>>(w33);

    // conv via tf32 mma: grid (12 y-tiles of 4 rows, 64 (b,r)), 512 thr
    // K=17: kx padded to 24 (WSS=28); K=33: kx padded to 40 (WSS=44)
    conv_mma<17, 0, 24, 28, true ><<<dim3(12, 64), 512>>>(x, b17, ksw, gk);
    conv_mma<33, 8, 40, 44, false><<<dim3(12, 64), 512>>>(x, b33, ksw, gk);

    gemm_attnz<1><<<dim3(48, 64), 256>>>(w2 + 16384, b2 + 128, wa + 128,
                                         ba + 1, wz + 512, bz + 4);
    gemm_attnz<0><<<dim3(48, 32), 256>>>(w2, b2, wa, ba, wz, bz);

    combine_kern<<<(NB * NR * NHW + 255) / 256, 256>>>(rdw, gr, out);
    stats_kern<<<NB, 256>>>(out, ga);
    final_kern<<<(NB * NR * NHW + 255) / 256, 256>>>(ga, out);
}

// round 7
// speedup vs baseline: 1.7864x; 1.3462x over previous
#include <cuda_runtime.h>
#include <math.h>

#define NB 8
#define NO 128
#define NR 8
#define NH 48
#define NHW 2304
#define NX 64

// ---- output layout (concatenated flattened outputs, float32) ----
#define OFF_ATTN 0
#define OFF_Q    147456
#define OFF_PR   294912
#define OFF_A    294920
#define OFF_OFF  442376
#define OFF_TH   442384
#define OFF_Z    737296

typedef unsigned long long ull;

// ---- device scratch (static, no runtime allocation) ----
__device__ unsigned d_rt17[NR * 17 * NO * 24];   // tf32, [r][ky][o][24]
__device__ unsigned d_rt33[NR * 33 * NO * 40];   // tf32, [r][ky][o][40]
__device__ float d_xout[NB * NO * NR * NHW];     // [b][c][r][hw]
__device__ float d_attn1[NB * NR * NHW];
__device__ float d_attn0[NB * 4 * NHW];
__device__ float d_z1[NB * 4 * NR * NHW];        // [b][l][r][hw]
__device__ float d_z0[NB * 4 * 4 * NHW];
__device__ float d_stats[NB * 4];                // m1, s1, m2, s2

__constant__ float c_offs[8] = {
    0.0f, 0.7853981633974483f, 1.5707963267948966f, 2.356194490192345f,
    3.141592653589793f, -2.356194490192345f, -1.5707963267948966f,
    -0.7853981633974483f};

#define LOG_SIGMA   1.1447298858494002f   // log(pi), f32
#define HALF_LOG2PI 0.9189385332046727f   // 0.5*log(2*pi), f32
#define PI_F        3.14159265358979323846f

// packed f32x2 helpers (FFMA2 is PTX-only; ptxas never auto-fuses)
#define FFMA2(acc, a, b) \
    asm("fma.rn.f32x2 %0, %1, %2, %0;" : "+l"(acc) : "l"(a), "l"(b))
#define PACK2(dst, lo, hi) \
    asm("mov.b64 %0, {%1, %2};" : "=l"(dst) : "f"(lo), "f"(hi))
#define UNPACK2(lo, hi, src) \
    asm("mov.b64 {%0, %1}, %2;" : "=f"(lo), "=f"(hi) : "l"(src))

// tf32 tensor-core helpers
__device__ __forceinline__ unsigned f2tf(float v) {
    unsigned r;
    asm("cvt.rn.tf32.f32 %0, %1;" : "=r"(r) : "f"(v));
    return r;
}
#define MMA_TF32(c, a0, a1, a2, a3, b0, b1)                                 \
    asm volatile(                                                           \
        "mma.sync.aligned.m16n8k8.row.col.f32.tf32.tf32.f32 "               \
        "{%0,%1,%2,%3}, {%4,%5,%6,%7}, {%8,%9}, {%0,%1,%2,%3};"             \
        : "+f"((c)[0]), "+f"((c)[1]), "+f"((c)[2]), "+f"((c)[3])            \
        : "r"(a0), "r"(a1), "r"(a2), "r"(a3), "r"(b0), "r"(b1))

// ============================================================
// K1: rotate kernels (bilinear grid_sample semantics, zero pad)
//   writes tf32 directly in mma-friendly padded layout
//   [r][ky][o][KXP] (kx >= K zero-filled)
// ============================================================
template <int K, int KXP>
__global__ void rotate_tf(const float* __restrict__ w) {
    constexpr int KK = K * K;
    unsigned* out = (K == 17) ? d_rt17 : d_rt33;
    int idx = blockIdx.x * blockDim.x + threadIdx.x;
    if (idx >= NR * K * NO * KXP) return;
    int kx = idx % KXP;
    int t = idx / KXP;
    int o = t % NO; t /= NO;
    int ky = t % K;
    int r = t / K;

    if (kx >= K) { out[idx] = 0u; return; }

    int i = ky, j = kx;
    float theta = 0.7853981633974483f * (float)r;  // (2*pi/8)*r in f32
    float c = cosf(theta), s = sinf(theta);
    float gy = (2.0f * (float)i + 1.0f) / (float)K - 1.0f;
    float gx = (2.0f * (float)j + 1.0f) / (float)K - 1.0f;
    float sx = c * gx - s * gy;
    float sy = s * gx + c * gy;
    float fx = ((sx + 1.0f) * (float)K - 1.0f) * 0.5f;
    float fy = ((sy + 1.0f) * (float)K - 1.0f) * 0.5f;
    int x0 = (int)floorf(fx);
    int y0 = (int)floorf(fy);
    float wx1 = fx - (float)x0;
    float wy1 = fy - (float)y0;
    const float* wo = w + o * KK;

    auto g = [&](int y, int x) -> float {
        if (y < 0 || y >= K || x < 0 || x >= K) return 0.0f;
        return wo[y * K + x];
    };
    float v = g(y0, x0) * (1.0f - wy1) * (1.0f - wx1)
            + g(y0, x0 + 1) * (1.0f - wy1) * wx1
            + g(y0 + 1, x0) * wy1 * (1.0f - wx1)
            + g(y0 + 1, x0 + 1) * wy1 * wx1;
    out[idx] = f2tf(v);
}

// ============================================================
// K2: group conv via tf32 mma.sync implicit-GEMM
//   block: one (b, r), M=128 o x N=96 spatial (2 rows x 48)
//   16 warps: wm in [0,8) x wn in [0,2); warp = 16 o x 48 n
//   A-fragments LDG'd straight from precomputed tf32 weights
//   (L1/L2 cached, reused by 24*8 blocks per r) -> no weight smem,
//   no syncthreads inside the K-loop.
// ============================================================
template <int K, int PAD, int KXP, bool FIRST>
__global__ __launch_bounds__(512, 2) void conv_mma(
    const float* __restrict__ x, const float* __restrict__ bias,
    const float* __restrict__ kw, const float* __restrict__ gk) {
    constexpr int XROWS = K + 1;
    constexpr int XCOLS = 48 + KXP;
    constexpr int NCH = KXP / 8;
    const unsigned* rt = (K == 17) ? d_rt17 : d_rt33;

    __shared__ unsigned xsT[XROWS * XCOLS];   // tf32 x tile

    int tid = threadIdx.x;
    int lane = tid & 31, wid = tid >> 5;
    int gid = lane >> 2, tig = lane & 3;
    int wm = wid & 7;      // o tile: [16*wm, 16*wm+16)
    int wn = wid >> 3;     // y row: y0 + wn
    int y0 = blockIdx.x * 2;
    int b = blockIdx.y >> 3, r = blockIdx.y & 7;

    // stage x tile as tf32 (zero-padded boundaries + kx padding region)
    const float* xb = x + b * NX * NX;
    for (int idx = tid; idx < XROWS * XCOLS; idx += 512) {
        int row = idx / XCOLS, col = idx - row * XCOLS;
        int gr = y0 + row - PAD, gc = col - PAD;
        float v = (gr >= 0 && gr < NX && gc >= 0 && gc < NX)
                      ? xb[gr * NX + gc] : 0.0f;
        xsT[idx] = f2tf(v);
    }
    __syncthreads();

    float acc[6][4];
#pragma unroll
    for (int j = 0; j < 6; ++j)
#pragma unroll
        for (int e = 0; e < 4; ++e) acc[j][e] = 0.0f;

#pragma unroll 1
    for (int ky = 0; ky < K; ++ky) {
        const unsigned* abase =
            rt + ((size_t)(r * K + ky) * NO + 16 * wm + gid) * KXP + tig;
        unsigned a[NCH][4];
#pragma unroll
        for (int kc = 0; kc < NCH; ++kc) {
            a[kc][0] = abase[kc * 8];
            a[kc][1] = abase[kc * 8 + 8 * KXP];
            a[kc][2] = abase[kc * 8 + 4];
            a[kc][3] = abase[kc * 8 + 8 * KXP + 4];
        }
        const unsigned* brow = xsT + (wn + ky) * XCOLS + gid + tig;
#pragma unroll
        for (int kc = 0; kc < NCH; ++kc) {
#pragma unroll
            for (int j = 0; j < 6; ++j) {
                const unsigned* bp = brow + kc * 8 + j * 8;
                MMA_TF32(acc[j], a[kc][0], a[kc][1], a[kc][2], a[kc][3],
                         bp[0], bp[4]);
            }
        }
    }

    // gumbel-softmax alpha over kernel sizes
    float l0 = (kw[0] + gk[0]) / 10.0f;
    float l1 = (kw[1] + gk[1]) / 10.0f;
    float mm = fmaxf(l0, l1);
    float e0 = expf(l0 - mm), e1 = expf(l1 - mm);
    float alpha = (FIRST ? e0 : e1) / (e0 + e1);

    int o_lo = 16 * wm + gid;
    int o_hi = o_lo + 8;
    float blo = bias[o_lo], bhi = bias[o_hi];
    int y = y0 + wn;

#pragma unroll
    for (int j = 0; j < 6; ++j) {
        int xc = j * 8 + 2 * tig;
#pragma unroll
        for (int half = 0; half < 2; ++half) {
            int o = half ? o_hi : o_lo;
            float bb = half ? bhi : blo;
            float v0 = acc[j][2 * half + 0] + bb;
            float v1 = acc[j][2 * half + 1] + bb;
            v0 = (v0 >= 0.0f) ? v0 : 0.01f * v0;
            v1 = (v1 >= 0.0f) ? v1 : 0.01f * v1;
            v0 *= alpha;
            v1 *= alpha;
            float2* p = (float2*)(d_xout + (((b * NO + o) * NR + r) * NHW)
                                  + y * 48 + xc);
            if (FIRST) {
                *p = make_float2(v0, v1);
            } else {
                float2 old = *p;
                *p = make_float2(old.x + v0, old.y + v1);
            }
        }
    }
}

// ============================================================
// K3: fused conv2(128x128) + lrelu + conva(1) + convz(4) heads
//   block: fixed (b, r, spatial row h); 256 thr = 16 o-grp x 16 n-grp
//   main GEMM loop uses FFMA2 over channel pairs (o, o+16)
// ============================================================
template <int BRANCH>
__global__ __launch_bounds__(256) void gemm_attnz(
    const float* __restrict__ w2, const float* __restrict__ b2,
    const float* __restrict__ wa, const float* __restrict__ ba,
    const float* __restrict__ wz, const float* __restrict__ bz) {
    constexpr int RCOUNT = BRANCH ? 8 : 4;
    constexpr int RSTEP = BRANCH ? 1 : 2;
    float* attn_out = BRANCH ? d_attn1 : d_attn0;
    float* z_out = BRANCH ? d_z1 : d_z0;

    __shared__ ull ws2[32 * 64];     // [cc][p][to]: pair (o=32p+to, o=32p+16+to)
    __shared__ float xt[128 * 48];   // [c][n]

    int tid = threadIdx.x;
    int to = tid & 15;
    int tn = tid >> 4;
    int h = blockIdx.x;
    int brs = blockIdx.y;
    int b = brs / RCOUNT;
    int rsub = brs - b * RCOUNT;
    int r = rsub * RSTEP;

    const float* xb = d_xout + ((b * NO) * NR + r) * NHW + h * 48;
    for (int idx = tid; idx < 6144; idx += 256) {
        int c = idx / 48, n = idx - c * 48;
        xt[idx] = xb[c * (NR * NHW) + n];
    }

    ull acc2[4][3];
#pragma unroll
    for (int p = 0; p < 4; ++p)
#pragma unroll
        for (int j = 0; j < 3; ++j) acc2[p][j] = 0ull;

    for (int kc = 0; kc < 4; ++kc) {
        __syncthreads();
        for (int idx = tid; idx < 2048; idx += 256) {
            int cc = idx >> 6, rest = idx & 63;
            int p = rest >> 4, t = rest & 15;
            float lo = w2[(32 * p + t) * 128 + kc * 32 + cc];
            float hi = w2[(32 * p + 16 + t) * 128 + kc * 32 + cc];
            ull pr;
            PACK2(pr, lo, hi);
            ws2[idx] = pr;
        }
        __syncthreads();
#pragma unroll 4
        for (int cc = 0; cc < 32; ++cc) {
            int k = kc * 32 + cc;
            ull xp[3];
#pragma unroll
            for (int j = 0; j < 3; ++j) {
                float v = xt[k * 48 + tn * 3 + j];
                PACK2(xp[j], v, v);
            }
#pragma unroll
            for (int p = 0; p < 4; ++p) {
                ull wv = ws2[cc * 64 + p * 16 + to];
                FFMA2(acc2[p][0], wv, xp[0]);
                FFMA2(acc2[p][1], wv, xp[1]);
                FFMA2(acc2[p][2], wv, xp[2]);
            }
        }
    }

    // epilogue: h = lrelu(acc + b2[o]); heads reduce over o
    float pa[3] = {0.f, 0.f, 0.f};
    float pz[4][3];
#pragma unroll
    for (int l = 0; l < 4; ++l)
#pragma unroll
        for (int j = 0; j < 3; ++j) pz[l][j] = 0.0f;

#pragma unroll
    for (int p = 0; p < 4; ++p) {
#pragma unroll
        for (int half = 0; half < 2; ++half) {
            int o = 32 * p + 16 * half + to;
            float bb = b2[o];
            float wav = wa[o];
            float w0 = wz[o], w1 = wz[128 + o], w2v = wz[256 + o],
                  w3 = wz[384 + o];
#pragma unroll
            for (int j = 0; j < 3; ++j) {
                float v0, v1;
                UNPACK2(v0, v1, acc2[p][j]);
                float hv = half ? v1 : v0;
                hv += bb;
                hv = (hv >= 0.0f) ? hv : 0.01f * hv;
                pa[j] = fmaf(wav, hv, pa[j]);
                pz[0][j] = fmaf(w0, hv, pz[0][j]);
                pz[1][j] = fmaf(w1, hv, pz[1][j]);
                pz[2][j] = fmaf(w2v, hv, pz[2][j]);
                pz[3][j] = fmaf(w3, hv, pz[3][j]);
            }
        }
    }

    // reduce across the 16 o-groups (lanes differing in bits 0..3)
#pragma unroll
    for (int m = 8; m >= 1; m >>= 1) {
#pragma unroll
        for (int j = 0; j < 3; ++j) {
            pa[j] += __shfl_xor_sync(0xffffffffu, pa[j], m);
#pragma unroll
            for (int l = 0; l < 4; ++l)
                pz[l][j] += __shfl_xor_sync(0xffffffffu, pz[l][j], m);
        }
    }

    if (to == 0) {
        int nbase = h * 48 + tn * 3;
#pragma unroll
        for (int j = 0; j < 3; ++j)
            attn_out[(b * RCOUNT + rsub) * NHW + nbase + j] = pa[j] + ba[0];
#pragma unroll
        for (int l = 0; l < 4; ++l)
#pragma unroll
            for (int j = 0; j < 3; ++j)
                z_out[((b * 4 + l) * RCOUNT + rsub) * NHW + nbase + j] =
                    pz[l][j] + bz[l];
    }
}

// ============================================================
// K4: scatter combine (betas) + p_r; writes attn, z, theta,
//     p_r, offsets directly into d_out
// ============================================================
__global__ void combine_kern(const float* __restrict__ rw,
                             const float* __restrict__ gr,
                             float* __restrict__ out) {
    int idx = blockIdx.x * blockDim.x + threadIdx.x;
    if (idx >= NB * NR * NHW) return;

    float l0 = (rw[0] + gr[0]) / 10.0f;
    float l1 = (rw[1] + gr[1]) / 10.0f;
    float mm = fmaxf(l0, l1);
    float e0 = expf(l0 - mm), e1 = expf(l1 - mm);
    float inv = 1.0f / (e0 + e1);
    float b0 = e0 * inv, b1 = e1 * inv;

    int b = idx / (NR * NHW);
    int rem = idx - b * (NR * NHW);
    int r = rem / NHW;
    int hw = rem - r * NHW;
    float off = c_offs[r];
    float t = off / PI_F;
    float pr = -0.5f * t * t - LOG_SIGMA - HALF_LOG2PI;

    float a = b1 * d_attn1[(b * NR + r) * NHW + hw];
    bool even = ((r & 1) == 0);
    if (even) a += b0 * d_attn0[(b * 4 + (r >> 1)) * NHW + hw];
    a += pr;
    out[OFF_ATTN + idx] = a;

    float zv[4];
#pragma unroll
    for (int l = 0; l < 4; ++l) {
        float z = b1 * d_z1[((b * 4 + l) * NR + r) * NHW + hw];
        if (even) z += b0 * d_z0[((b * 4 + l) * 4 + (r >> 1)) * NHW + hw];
        zv[l] = z;
        out[OFF_Z + ((b * 4 + l) * NR + r) * NHW + hw] = z;
    }
    out[OFF_TH + ((b * 2 + 0) * NR + r) * NHW + hw] = zv[0] + off;
    out[OFF_TH + ((b * 2 + 1) * NR + r) * NHW + hw] = zv[1];

    if (idx < 8) {
        float o2 = c_offs[idx];
        float t2 = o2 / PI_F;
        out[OFF_PR + idx] = -0.5f * t2 * t2 - LOG_SIGMA - HALF_LOG2PI;
        out[OFF_OFF + idx] = o2;
    }
}

// ============================================================
// K5: per-batch softmax stats (max / sumexp, two distributions)
// ============================================================
__global__ void stats_kern(const float* __restrict__ out,
                           const float* __restrict__ g) {
    __shared__ float sm[256];
    int b = blockIdx.x, tid = threadIdx.x;
    const float* a = out + OFF_ATTN + b * (NR * NHW);
    const float* gb = g + b * (NR * NHW);

    float m1 = -1e30f, m2 = -1e30f;
    for (int i = tid; i < NR * NHW; i += 256) {
        float v = a[i];
        m1 = fmaxf(m1, v);
        m2 = fmaxf(m2, v + gb[i]);
    }
    sm[tid] = m1; __syncthreads();
    for (int s = 128; s > 0; s >>= 1) {
        if (tid < s) sm[tid] = fmaxf(sm[tid], sm[tid + s]);
        __syncthreads();
    }
    m1 = sm[0]; __syncthreads();
    sm[tid] = m2; __syncthreads();
    for (int s = 128; s > 0; s >>= 1) {
        if (tid < s) sm[tid] = fmaxf(sm[tid], sm[tid + s]);
        __syncthreads();
    }
    m2 = sm[0]; __syncthreads();

    float s1 = 0.0f, s2 = 0.0f;
    for (int i = tid; i < NR * NHW; i += 256) {
        float v = a[i];
        s1 += expf(v - m1);
        s2 += expf(v + gb[i] - m2);
    }
    sm[tid] = s1; __syncthreads();
    for (int s = 128; s > 0; s >>= 1) {
        if (tid < s) sm[tid] += sm[tid + s];
        __syncthreads();
    }
    s1 = sm[0]; __syncthreads();
    sm[tid] = s2; __syncthreads();
    for (int s = 128; s > 0; s >>= 1) {
        if (tid < s) sm[tid] += sm[tid + s];
        __syncthreads();
    }
    s2 = sm[0];

    if (tid == 0) {
        d_stats[b * 4 + 0] = m1;
        d_stats[b * 4 + 1] = s1;
        d_stats[b * 4 + 2] = m2;
        d_stats[b * 4 + 3] = s2;
    }
}

// ============================================================
// K6: q_t_r (log_softmax) + a_sampled (gumbel softmax)
// ============================================================
__global__ void final_kern(const float* __restrict__ g,
                           float* __restrict__ out) {
    int idx = blockIdx.x * blockDim.x + threadIdx.x;
    if (idx >= NB * NR * NHW) return;
    int b = idx / (NR * NHW);
    float v = out[OFF_ATTN + idx];
    out[OFF_Q + idx] = (v - d_stats[b * 4 + 0]) - logf(d_stats[b * 4 + 1]);
    out[OFF_A + idx] =
        expf(v + g[idx] - d_stats[b * 4 + 2]) / d_stats[b * 4 + 3];
}

// ============================================================
extern "C" void kernel_launch(void* const* d_in, const int* in_sizes, int n_in,
                              void* d_out, int out_size) {
    const float* x   = (const float*)d_in[0];
    const float* ksw = (const float*)d_in[1];
    const float* rdw = (const float*)d_in[2];
    const float* w17 = (const float*)d_in[3];
    const float* b17 = (const float*)d_in[4];
    const float* w33 = (const float*)d_in[5];
    const float* b33 = (const float*)d_in[6];
    const float* w2  = (const float*)d_in[7];
    const float* b2  = (const float*)d_in[8];
    const float* wa  = (const float*)d_in[9];
    const float* ba  = (const float*)d_in[10];
    const float* wz  = (const float*)d_in[11];
    const float* bz  = (const float*)d_in[12];
    const float* gk  = (const float*)d_in[13];
    const float* gr  = (const float*)d_in[14];
    const float* ga  = (const float*)d_in[15];
    float* out = (float*)d_out;

    rotate_tf<17, 24><<<(NR * 17 * NO * 24 + 255) / 256, 256>>>(w17);
    rotate_tf<33, 40><<<(NR * 33 * NO * 40 + 255) / 256, 256>>>(w33);

    // conv via tf32 mma: grid (24 y-tiles of 2 rows, 64 (b,r)), 512 thr
    conv_mma<17, 0, 24, true ><<<dim3(24, 64), 512>>>(x, b17, ksw, gk);
    conv_mma<33, 8, 40, false><<<dim3(24, 64), 512>>>(x, b33, ksw, gk);

    gemm_attnz<1><<<dim3(48, 64), 256>>>(w2 + 16384, b2 + 128, wa + 128,
                                         ba + 1, wz + 512, bz + 4);
    gemm_attnz<0><<<dim3(48, 32), 256>>>(w2, b2, wa, ba, wz, bz);

    combine_kern<<<(NB * NR * NHW + 255) / 256, 256>>>(rdw, gr, out);
    stats_kern<<<NB, 256>>>(out, ga);
    final_kern<<<(NB * NR * NHW + 255) / 256, 256>>>(ga, out);
}

// round 8
// speedup vs baseline: 1.9587x; 1.0965x over previous
#include <cuda_runtime.h>
#include <math.h>

#define NB 8
#define NO 128
#define NR 8
#define NH 48
#define NHW 2304
#define NX 64

// ---- output layout (concatenated flattened outputs, float32) ----
#define OFF_ATTN 0
#define OFF_Q    147456
#define OFF_PR   294912
#define OFF_A    294920
#define OFF_OFF  442376
#define OFF_TH   442384
#define OFF_Z    737296

typedef unsigned long long ull;

// ---- device scratch (static, no runtime allocation) ----
// tf32 weights pre-swizzled in mma A-fragment order:
//   [r][ky][wset(8)][kc(NCH)][lane(32)] -> uint4 (a0,a1,a2,a3)
__device__ uint4 d_rt17[NR * 17 * 8 * 3 * 32];
__device__ uint4 d_rt33[NR * 33 * 8 * 5 * 32];
__device__ float d_xout[NB * NO * NR * NHW];     // [b][c][r][hw]
__device__ float d_attn1[NB * NR * NHW];
__device__ float d_attn0[NB * 4 * NHW];
__device__ float d_z1[NB * 4 * NR * NHW];        // [b][l][r][hw]
__device__ float d_z0[NB * 4 * 4 * NHW];
__device__ float d_stats[NB * 4];                // m1, s1, m2, s2

__constant__ float c_offs[8] = {
    0.0f, 0.7853981633974483f, 1.5707963267948966f, 2.356194490192345f,
    3.141592653589793f, -2.356194490192345f, -1.5707963267948966f,
    -0.7853981633974483f};

#define LOG_SIGMA   1.1447298858494002f   // log(pi), f32
#define HALF_LOG2PI 0.9189385332046727f   // 0.5*log(2*pi), f32
#define PI_F        3.14159265358979323846f

// packed f32x2 helpers (FFMA2 is PTX-only; ptxas never auto-fuses)
#define FFMA2(acc, a, b) \
    asm("fma.rn.f32x2 %0, %1, %2, %0;" : "+l"(acc) : "l"(a), "l"(b))
#define PACK2(dst, lo, hi) \
    asm("mov.b64 %0, {%1, %2};" : "=l"(dst) : "f"(lo), "f"(hi))
#define UNPACK2(lo, hi, src) \
    asm("mov.b64 {%0, %1}, %2;" : "=f"(lo), "=f"(hi) : "l"(src))

// tf32 tensor-core helpers
__device__ __forceinline__ unsigned f2tf(float v) {
    unsigned r;
    asm("cvt.rn.tf32.f32 %0, %1;" : "=r"(r) : "f"(v));
    return r;
}
#define MMA_TF32(c, a0, a1, a2, a3, b0, b1)                                 \
    asm volatile(                                                           \
        "mma.sync.aligned.m16n8k8.row.col.f32.tf32.tf32.f32 "               \
        "{%0,%1,%2,%3}, {%4,%5,%6,%7}, {%8,%9}, {%0,%1,%2,%3};"             \
        : "+f"((c)[0]), "+f"((c)[1]), "+f"((c)[2]), "+f"((c)[3])            \
        : "r"(a0), "r"(a1), "r"(a2), "r"(a3), "r"(b0), "r"(b1))

// ============================================================
// K1: rotate kernels (bilinear grid_sample semantics, zero pad)
//   emits tf32 weights directly in per-lane mma fragment order:
//   word index = ((((r*K+ky)*8+wset)*NCH+kc)*32+lane)*4+q
//   value(q)  = w_rot[o = 16*wset + (lane>>2) + 8*(q&1)]
//                    [kx = kc*8 + (lane&3) + 4*(q>>1)]
// ============================================================
template <int K, int NCH>
__global__ void rotate_tf(const float* __restrict__ w) {
    constexpr int KK = K * K;
    unsigned* out = (K == 17) ? (unsigned*)d_rt17 : (unsigned*)d_rt33;
    int idx = blockIdx.x * blockDim.x + threadIdx.x;
    if (idx >= NR * K * 8 * NCH * 128) return;

    int q = idx & 3;
    int lane = (idx >> 2) & 31;
    int t = idx >> 7;
    int kc = t % NCH; t /= NCH;
    int wset = t & 7; t >>= 3;
    int ky = t % K;
    int r = t / K;

    int o = 16 * wset + (lane >> 2) + 8 * (q & 1);
    int kx = kc * 8 + (lane & 3) + 4 * (q >> 1);
    if (kx >= K) { out[idx] = 0u; return; }

    int i = ky, j = kx;
    float theta = 0.7853981633974483f * (float)r;  // (2*pi/8)*r in f32
    float c = cosf(theta), s = sinf(theta);
    float gy = (2.0f * (float)i + 1.0f) / (float)K - 1.0f;
    float gx = (2.0f * (float)j + 1.0f) / (float)K - 1.0f;
    float sx = c * gx - s * gy;
    float sy = s * gx + c * gy;
    float fx = ((sx + 1.0f) * (float)K - 1.0f) * 0.5f;
    float fy = ((sy + 1.0f) * (float)K - 1.0f) * 0.5f;
    int x0 = (int)floorf(fx);
    int y0 = (int)floorf(fy);
    float wx1 = fx - (float)x0;
    float wy1 = fy - (float)y0;
    const float* wo = w + o * KK;

    auto g = [&](int y, int x) -> float {
        if (y < 0 || y >= K || x < 0 || x >= K) return 0.0f;
        return wo[y * K + x];
    };
    float v = g(y0, x0) * (1.0f - wy1) * (1.0f - wx1)
            + g(y0, x0 + 1) * (1.0f - wy1) * wx1
            + g(y0 + 1, x0) * wy1 * (1.0f - wx1)
            + g(y0 + 1, x0 + 1) * wy1 * wx1;
    out[idx] = f2tf(v);
}

// ============================================================
// K2: group conv via tf32 mma.sync implicit-GEMM
//   block: one (b, r), M=128 o x N=96 spatial (2 rows x 48), 256 thr
//   8 warps: wm4 = wid>>1 in [0,4) covers 32 o; wn = wid&1 row
//   A-fragments: ONE coalesced LDG.128 per lane (pre-swizzled),
//   each B fragment load feeds TWO mma (M=32 reuse).
// ============================================================
template <int K, int PAD, int NCH, bool FIRST>
__global__ __launch_bounds__(256, 3) void conv_mma(
    const float* __restrict__ x, const float* __restrict__ bias,
    const float* __restrict__ kw, const float* __restrict__ gk) {
    constexpr int KXP = NCH * 8;
    constexpr int XROWS = K + 1;
    constexpr int XCOLS = 48 + KXP;
    const uint4* rt4 = (K == 17) ? d_rt17 : d_rt33;

    __shared__ unsigned xsT[XROWS * XCOLS];   // tf32 x tile

    int tid = threadIdx.x;
    int lane = tid & 31, wid = tid >> 5;
    int gid = lane >> 2, tig = lane & 3;
    int wm4 = wid >> 1;    // o tile: [32*wm4, 32*wm4+32)
    int wn = wid & 1;      // y row: y0 + wn
    int y0 = blockIdx.x * 2;
    int b = blockIdx.y >> 3, r = blockIdx.y & 7;

    // stage x tile as tf32 (zero-padded boundaries + kx padding region)
    const float* xb = x + b * NX * NX;
    for (int idx = tid; idx < XROWS * XCOLS; idx += 256) {
        int row = idx / XCOLS, col = idx - row * XCOLS;
        int gr = y0 + row - PAD, gc = col - PAD;
        float v = (gr >= 0 && gr < NX && gc >= 0 && gc < NX)
                      ? xb[gr * NX + gc] : 0.0f;
        xsT[idx] = f2tf(v);
    }
    __syncthreads();

    float acc[2][6][4];
#pragma unroll
    for (int m = 0; m < 2; ++m)
#pragma unroll
        for (int j = 0; j < 6; ++j)
#pragma unroll
            for (int e = 0; e < 4; ++e) acc[m][j][e] = 0.0f;

#pragma unroll 1
    for (int ky = 0; ky < K; ++ky) {
        const uint4* ap =
            rt4 + ((size_t)((r * K + ky) * 8 + 2 * wm4) * NCH) * 32 + lane;
        const unsigned* brow = xsT + (wn + ky) * XCOLS + gid + tig;
#pragma unroll
        for (int kc = 0; kc < NCH; ++kc) {
            uint4 A0 = ap[kc * 32];
            uint4 A1 = ap[(NCH + kc) * 32];
#pragma unroll
            for (int j = 0; j < 6; ++j) {
                unsigned b0 = brow[kc * 8 + j * 8];
                unsigned b1 = brow[kc * 8 + j * 8 + 4];
                MMA_TF32(acc[0][j], A0.x, A0.y, A0.z, A0.w, b0, b1);
                MMA_TF32(acc[1][j], A1.x, A1.y, A1.z, A1.w, b0, b1);
            }
        }
    }

    // gumbel-softmax alpha over kernel sizes
    float l0 = (kw[0] + gk[0]) / 10.0f;
    float l1 = (kw[1] + gk[1]) / 10.0f;
    float mm = fmaxf(l0, l1);
    float e0 = expf(l0 - mm), e1 = expf(l1 - mm);
    float alpha = (FIRST ? e0 : e1) / (e0 + e1);

    int y = y0 + wn;
#pragma unroll
    for (int m = 0; m < 2; ++m) {
        int o_lo = 32 * wm4 + 16 * m + gid;
        int o_hi = o_lo + 8;
        float blo = bias[o_lo], bhi = bias[o_hi];
#pragma unroll
        for (int j = 0; j < 6; ++j) {
            int xc = j * 8 + 2 * tig;
#pragma unroll
            for (int half = 0; half < 2; ++half) {
                int o = half ? o_hi : o_lo;
                float bb = half ? bhi : blo;
                float v0 = acc[m][j][2 * half + 0] + bb;
                float v1 = acc[m][j][2 * half + 1] + bb;
                v0 = (v0 >= 0.0f) ? v0 : 0.01f * v0;
                v1 = (v1 >= 0.0f) ? v1 : 0.01f * v1;
                v0 *= alpha;
                v1 *= alpha;
                float2* p = (float2*)(d_xout
                                      + (((b * NO + o) * NR + r) * NHW)
                                      + y * 48 + xc);
                if (FIRST) {
                    *p = make_float2(v0, v1);
                } else {
                    float2 old = *p;
                    *p = make_float2(old.x + v0, old.y + v1);
                }
            }
        }
    }
}

// ============================================================
// K3: fused conv2(128x128) + lrelu + conva(1) + convz(4) heads
//   block: fixed (b, r, spatial row h); 256 thr = 16 o-grp x 16 n-grp
//   main GEMM loop uses FFMA2 over channel pairs (o, o+16)
// ============================================================
template <int BRANCH>
__global__ __launch_bounds__(256) void gemm_attnz(
    const float* __restrict__ w2, const float* __restrict__ b2,
    const float* __restrict__ wa, const float* __restrict__ ba,
    const float* __restrict__ wz, const float* __restrict__ bz) {
    constexpr int RCOUNT = BRANCH ? 8 : 4;
    constexpr int RSTEP = BRANCH ? 1 : 2;
    float* attn_out = BRANCH ? d_attn1 : d_attn0;
    float* z_out = BRANCH ? d_z1 : d_z0;

    __shared__ ull ws2[32 * 64];     // [cc][p][to]: pair (o=32p+to, o=32p+16+to)
    __shared__ float xt[128 * 48];   // [c][n]

    int tid = threadIdx.x;
    int to = tid & 15;
    int tn = tid >> 4;
    int h = blockIdx.x;
    int brs = blockIdx.y;
    int b = brs / RCOUNT;
    int rsub = brs - b * RCOUNT;
    int r = rsub * RSTEP;

    const float* xb = d_xout + ((b * NO) * NR + r) * NHW + h * 48;
    for (int idx = tid; idx < 6144; idx += 256) {
        int c = idx / 48, n = idx - c * 48;
        xt[idx] = xb[c * (NR * NHW) + n];
    }

    ull acc2[4][3];
#pragma unroll
    for (int p = 0; p < 4; ++p)
#pragma unroll
        for (int j = 0; j < 3; ++j) acc2[p][j] = 0ull;

    for (int kc = 0; kc < 4; ++kc) {
        __syncthreads();
        for (int idx = tid; idx < 2048; idx += 256) {
            int cc = idx >> 6, rest = idx & 63;
            int p = rest >> 4, t = rest & 15;
            float lo = w2[(32 * p + t) * 128 + kc * 32 + cc];
            float hi = w2[(32 * p + 16 + t) * 128 + kc * 32 + cc];
            ull pr;
            PACK2(pr, lo, hi);
            ws2[idx] = pr;
        }
        __syncthreads();
#pragma unroll 4
        for (int cc = 0; cc < 32; ++cc) {
            int k = kc * 32 + cc;
            ull xp[3];
#pragma unroll
            for (int j = 0; j < 3; ++j) {
                float v = xt[k * 48 + tn * 3 + j];
                PACK2(xp[j], v, v);
            }
#pragma unroll
            for (int p = 0; p < 4; ++p) {
                ull wv = ws2[cc * 64 + p * 16 + to];
                FFMA2(acc2[p][0], wv, xp[0]);
                FFMA2(acc2[p][1], wv, xp[1]);
                FFMA2(acc2[p][2], wv, xp[2]);
            }
        }
    }

    // epilogue: h = lrelu(acc + b2[o]); heads reduce over o
    float pa[3] = {0.f, 0.f, 0.f};
    float pz[4][3];
#pragma unroll
    for (int l = 0; l < 4; ++l)
#pragma unroll
        for (int j = 0; j < 3; ++j) pz[l][j] = 0.0f;

#pragma unroll
    for (int p = 0; p < 4; ++p) {
#pragma unroll
        for (int half = 0; half < 2; ++half) {
            int o = 32 * p + 16 * half + to;
            float bb = b2[o];
            float wav = wa[o];
            float w0 = wz[o], w1 = wz[128 + o], w2v = wz[256 + o],
                  w3 = wz[384 + o];
#pragma unroll
            for (int j = 0; j < 3; ++j) {
                float v0, v1;
                UNPACK2(v0, v1, acc2[p][j]);
                float hv = half ? v1 : v0;
                hv += bb;
                hv = (hv >= 0.0f) ? hv : 0.01f * hv;
                pa[j] = fmaf(wav, hv, pa[j]);
                pz[0][j] = fmaf(w0, hv, pz[0][j]);
                pz[1][j] = fmaf(w1, hv, pz[1][j]);
                pz[2][j] = fmaf(w2v, hv, pz[2][j]);
                pz[3][j] = fmaf(w3, hv, pz[3][j]);
            }
        }
    }

    // reduce across the 16 o-groups (lanes differing in bits 0..3)
#pragma unroll
    for (int m = 8; m >= 1; m >>= 1) {
#pragma unroll
        for (int j = 0; j < 3; ++j) {
            pa[j] += __shfl_xor_sync(0xffffffffu, pa[j], m);
#pragma unroll
            for (int l = 0; l < 4; ++l)
                pz[l][j] += __shfl_xor_sync(0xffffffffu, pz[l][j], m);
        }
    }

    if (to == 0) {
        int nbase = h * 48 + tn * 3;
#pragma unroll
        for (int j = 0; j < 3; ++j)
            attn_out[(b * RCOUNT + rsub) * NHW + nbase + j] = pa[j] + ba[0];
#pragma unroll
        for (int l = 0; l < 4; ++l)
#pragma unroll
            for (int j = 0; j < 3; ++j)
                z_out[((b * 4 + l) * RCOUNT + rsub) * NHW + nbase + j] =
                    pz[l][j] + bz[l];
    }
}

// ============================================================
// K4: scatter combine (betas) + p_r; writes attn, z, theta,
//     p_r, offsets directly into d_out
// ============================================================
__global__ void combine_kern(const float* __restrict__ rw,
                             const float* __restrict__ gr,
                             float* __restrict__ out) {
    int idx = blockIdx.x * blockDim.x + threadIdx.x;
    if (idx >= NB * NR * NHW) return;

    float l0 = (rw[0] + gr[0]) / 10.0f;
    float l1 = (rw[1] + gr[1]) / 10.0f;
    float mm = fmaxf(l0, l1);
    float e0 = expf(l0 - mm), e1 = expf(l1 - mm);
    float inv = 1.0f / (e0 + e1);
    float b0 = e0 * inv, b1 = e1 * inv;

    int b = idx / (NR * NHW);
    int rem = idx - b * (NR * NHW);
    int r = rem / NHW;
    int hw = rem - r * NHW;
    float off = c_offs[r];
    float t = off / PI_F;
    float pr = -0.5f * t * t - LOG_SIGMA - HALF_LOG2PI;

    float a = b1 * d_attn1[(b * NR + r) * NHW + hw];
    bool even = ((r & 1) == 0);
    if (even) a += b0 * d_attn0[(b * 4 + (r >> 1)) * NHW + hw];
    a += pr;
    out[OFF_ATTN + idx] = a;

    float zv[4];
#pragma unroll
    for (int l = 0; l < 4; ++l) {
        float z = b1 * d_z1[((b * 4 + l) * NR + r) * NHW + hw];
        if (even) z += b0 * d_z0[((b * 4 + l) * 4 + (r >> 1)) * NHW + hw];
        zv[l] = z;
        out[OFF_Z + ((b * 4 + l) * NR + r) * NHW + hw] = z;
    }
    out[OFF_TH + ((b * 2 + 0) * NR + r) * NHW + hw] = zv[0] + off;
    out[OFF_TH + ((b * 2 + 1) * NR + r) * NHW + hw] = zv[1];

    if (idx < 8) {
        float o2 = c_offs[idx];
        float t2 = o2 / PI_F;
        out[OFF_PR + idx] = -0.5f * t2 * t2 - LOG_SIGMA - HALF_LOG2PI;
        out[OFF_OFF + idx] = o2;
    }
}

// ============================================================
// K5: per-batch softmax stats (max / sumexp, two distributions)
// ============================================================
__global__ void stats_kern(const float* __restrict__ out,
                           const float* __restrict__ g) {
    __shared__ float sm[256];
    int b = blockIdx.x, tid = threadIdx.x;
    const float* a = out + OFF_ATTN + b * (NR * NHW);
    const float* gb = g + b * (NR * NHW);

    float m1 = -1e30f, m2 = -1e30f;
    for (int i = tid; i < NR * NHW; i += 256) {
        float v = a[i];
        m1 = fmaxf(m1, v);
        m2 = fmaxf(m2, v + gb[i]);
    }
    sm[tid] = m1; __syncthreads();
    for (int s = 128; s > 0; s >>= 1) {
        if (tid < s) sm[tid] = fmaxf(sm[tid], sm[tid + s]);
        __syncthreads();
    }
    m1 = sm[0]; __syncthreads();
    sm[tid] = m2; __syncthreads();
    for (int s = 128; s > 0; s >>= 1) {
        if (tid < s) sm[tid] = fmaxf(sm[tid], sm[tid + s]);
        __syncthreads();
    }
    m2 = sm[0]; __syncthreads();

    float s1 = 0.0f, s2 = 0.0f;
    for (int i = tid; i < NR * NHW; i += 256) {
        float v = a[i];
        s1 += expf(v - m1);
        s2 += expf(v + gb[i] - m2);
    }
    sm[tid] = s1; __syncthreads();
    for (int s = 128; s > 0; s >>= 1) {
        if (tid < s) sm[tid] += sm[tid + s];
        __syncthreads();
    }
    s1 = sm[0]; __syncthreads();
    sm[tid] = s2; __syncthreads();
    for (int s = 128; s > 0; s >>= 1) {
        if (tid < s) sm[tid] += sm[tid + s];
        __syncthreads();
    }
    s2 = sm[0];

    if (tid == 0) {
        d_stats[b * 4 + 0] = m1;
        d_stats[b * 4 + 1] = s1;
        d_stats[b * 4 + 2] = m2;
        d_stats[b * 4 + 3] = s2;
    }
}

// ============================================================
// K6: q_t_r (log_softmax) + a_sampled (gumbel softmax)
// ============================================================
__global__ void final_kern(const float* __restrict__ g,
                           float* __restrict__ out) {
    int idx = blockIdx.x * blockDim.x + threadIdx.x;
    if (idx >= NB * NR * NHW) return;
    int b = idx / (NR * NHW);
    float v = out[OFF_ATTN + idx];
    out[OFF_Q + idx] = (v - d_stats[b * 4 + 0]) - logf(d_stats[b * 4 + 1]);
    out[OFF_A + idx] =
        expf(v + g[idx] - d_stats[b * 4 + 2]) / d_stats[b * 4 + 3];
}

// ============================================================
extern "C" void kernel_launch(void* const* d_in, const int* in_sizes, int n_in,
                              void* d_out, int out_size) {
    const float* x   = (const float*)d_in[0];
    const float* ksw = (const float*)d_in[1];
    const float* rdw = (const float*)d_in[2];
    const float* w17 = (const float*)d_in[3];
    const float* b17 = (const float*)d_in[4];
    const float* w33 = (const float*)d_in[5];
    const float* b33 = (const float*)d_in[6];
    const float* w2  = (const float*)d_in[7];
    const float* b2  = (const float*)d_in[8];
    const float* wa  = (const float*)d_in[9];
    const float* ba  = (const float*)d_in[10];
    const float* wz  = (const float*)d_in[11];
    const float* bz  = (const float*)d_in[12];
    const float* gk  = (const float*)d_in[13];
    const float* gr  = (const float*)d_in[14];
    const float* ga  = (const float*)d_in[15];
    float* out = (float*)d_out;

    // rotate + fragment-swizzle: word counts
    //   K=17, NCH=3: 8*17*8*3*128 = 417792
    //   K=33, NCH=5: 8*33*8*5*128 = 1351680
    rotate_tf<17, 3><<<(417792 + 255) / 256, 256>>>(w17);
    rotate_tf<33, 5><<<(1351680 + 255) / 256, 256>>>(w33);

    // conv via tf32 mma: grid (24 y-tiles of 2 rows, 64 (b,r)), 256 thr
    conv_mma<17, 0, 3, true ><<<dim3(24, 64), 256>>>(x, b17, ksw, gk);
    conv_mma<33, 8, 5, false><<<dim3(24, 64), 256>>>(x, b33, ksw, gk);

    gemm_attnz<1><<<dim3(48, 64), 256>>>(w2 + 16384, b2 + 128, wa + 128,
                                         ba + 1, wz + 512, bz + 4);
    gemm_attnz<0><<<dim3(48, 32), 256>>>(w2, b2, wa, ba, wz, bz);

    combine_kern<<<(NB * NR * NHW + 255) / 256, 256>>>(rdw, gr, out);
    stats_kern<<<NB, 256>>>(out, ga);
    final_kern<<<(NB * NR * NHW + 255) / 256, 256>>>(ga, out);
}

// round 9
// speedup vs baseline: 3.6114x; 1.8438x over previous
#include <cuda_runtime.h>
#include <math.h>

#define NB 8
#define NO 128
#define NR 8
#define NH 48
#define NHW 2304
#define NX 64

// ---- output layout (concatenated flattened outputs, float32) ----
#define OFF_ATTN 0
#define OFF_Q    147456
#define OFF_PR   294912
#define OFF_A    294920
#define OFF_OFF  442376
#define OFF_TH   442384
#define OFF_Z    737296

// ---- device scratch (static, no runtime allocation) ----
// tf32 conv weights, flattened-k mma fragment order:
//   [r][wset(8)][kc][lane(32)] -> uint4 (a0,a1,a2,a3)
//   K=17: NCHK=37 (k padded 289->296); K=33: NCHK=137 (1089->1096)
__device__ uint4 d_rt17[NR * 8 * 37 * 32];
__device__ uint4 d_rt33[NR * 8 * 137 * 32];
// tf32 conv2 weights in fragment order: [branch][wset(8)][kc(16)][lane(32)]
__device__ uint4 d_w2f[2 * 8 * 16 * 32];
__device__ float d_xout[NB * NO * NR * NHW];     // [b][c][r][hw]
__device__ float d_attn1[NB * NR * NHW];
__device__ float d_attn0[NB * 4 * NHW];
__device__ float d_z1[NB * 4 * NR * NHW];        // [b][l][r][hw]
__device__ float d_z0[NB * 4 * 4 * NHW];
__device__ float d_stats[NB * 4];                // m1, s1, m2, s2

__constant__ float c_offs[8] = {
    0.0f, 0.7853981633974483f, 1.5707963267948966f, 2.356194490192345f,
    3.141592653589793f, -2.356194490192345f, -1.5707963267948966f,
    -0.7853981633974483f};

#define LOG_SIGMA   1.1447298858494002f   // log(pi), f32
#define HALF_LOG2PI 0.9189385332046727f   // 0.5*log(2*pi), f32
#define PI_F        3.14159265358979323846f

// tf32 tensor-core helpers
__device__ __forceinline__ unsigned f2tf(float v) {
    unsigned r;
    asm("cvt.rn.tf32.f32 %0, %1;" : "=r"(r) : "f"(v));
    return r;
}
#define MMA_TF32(c, a0, a1, a2, a3, b0, b1)                                 \
    asm volatile(                                                           \
        "mma.sync.aligned.m16n8k8.row.col.f32.tf32.tf32.f32 "               \
        "{%0,%1,%2,%3}, {%4,%5,%6,%7}, {%8,%9}, {%0,%1,%2,%3};"             \
        : "+f"((c)[0]), "+f"((c)[1]), "+f"((c)[2]), "+f"((c)[3])            \
        : "r"(a0), "r"(a1), "r"(a2), "r"(a3), "r"(b0), "r"(b1))

// ============================================================
// K1: rotate kernels (bilinear grid_sample, zero pad) -> tf32
//   fragment order over FLATTENED k = ky*K + kx:
//   word idx = (((r*8+wset)*NCHK+kc)*32+lane)*4+q
//   o  = 16*wset + (lane>>2) + 8*(q&1)
//   k  = kc*8 + (lane&3) + 4*(q>>1);  k >= K*K -> 0
// ============================================================
template <int K, int NCHK>
__global__ void rotate_tf(const float* __restrict__ w) {
    constexpr int KK = K * K;
    unsigned* out = (K == 17) ? (unsigned*)d_rt17 : (unsigned*)d_rt33;
    int idx = blockIdx.x * blockDim.x + threadIdx.x;
    if (idx >= NR * 8 * NCHK * 128) return;

    int q = idx & 3;
    int lane = (idx >> 2) & 31;
    int t = idx >> 7;
    int kc = t % NCHK; t /= NCHK;
    int wset = t & 7;
    int r = t >> 3;

    int o = 16 * wset + (lane >> 2) + 8 * (q & 1);
    int k = kc * 8 + (lane & 3) + 4 * (q >> 1);
    if (k >= KK) { out[idx] = 0u; return; }
    int ky = k / K;
    int kx = k - ky * K;

    int i = ky, j = kx;
    float theta = 0.7853981633974483f * (float)r;  // (2*pi/8)*r in f32
    float c = cosf(theta), s = sinf(theta);
    float gy = (2.0f * (float)i + 1.0f) / (float)K - 1.0f;
    float gx = (2.0f * (float)j + 1.0f) / (float)K - 1.0f;
    float sx = c * gx - s * gy;
    float sy = s * gx + c * gy;
    float fx = ((sx + 1.0f) * (float)K - 1.0f) * 0.5f;
    float fy = ((sy + 1.0f) * (float)K - 1.0f) * 0.5f;
    int x0 = (int)floorf(fx);
    int y0 = (int)floorf(fy);
    float wx1 = fx - (float)x0;
    float wy1 = fy - (float)y0;
    const float* wo = w + o * KK;

    auto g = [&](int y, int x) -> float {
        if (y < 0 || y >= K || x < 0 || x >= K) return 0.0f;
        return wo[y * K + x];
    };
    float v = g(y0, x0) * (1.0f - wy1) * (1.0f - wx1)
            + g(y0, x0 + 1) * (1.0f - wy1) * wx1
            + g(y0 + 1, x0) * wy1 * (1.0f - wx1)
            + g(y0 + 1, x0 + 1) * wy1 * wx1;
    out[idx] = f2tf(v);
}

// ============================================================
// K1b: conv2 weights -> tf32 fragment order
//   word idx = (((br*8+wset)*16+kc)*32+lane)*4+q
//   o = 16*wset + (lane>>2) + 8*(q&1); c = kc*8 + (lane&3) + 4*(q>>1)
// ============================================================
__global__ void w2_frag(const float* __restrict__ w2) {
    unsigned* out = (unsigned*)d_w2f;
    int idx = blockIdx.x * blockDim.x + threadIdx.x;
    if (idx >= 2 * 8 * 16 * 128) return;
    int q = idx & 3;
    int lane = (idx >> 2) & 31;
    int t = idx >> 7;
    int kc = t % 16; t /= 16;
    int wset = t & 7;
    int br = t >> 3;
    int o = 16 * wset + (lane >> 2) + 8 * (q & 1);
    int c = kc * 8 + (lane & 3) + 4 * (q >> 1);
    out[idx] = f2tf(w2[br * 16384 + o * 128 + c]);
}

// ============================================================
// K2: group conv via tf32 mma.sync implicit-GEMM, flattened k
//   block: one (b, r), M=128 o x N=96 spatial (2 rows x 48), 256 thr
//   8 warps: wm4 = wid>>1 (32 o), wn = wid&1 (y row)
//   chunk loop over k (8 per chunk, NO kx padding), distance-1
//   A-fragment prefetch; per-lane (row,col) trackers give the
//   im2col B address with cheap wrap increments.
// ============================================================
template <int K, int PAD, int NCHK, bool FIRST>
__global__ __launch_bounds__(256, 3) void conv_mma(
    const float* __restrict__ x, const float* __restrict__ bias,
    const float* __restrict__ kw, const float* __restrict__ gk) {
    constexpr int XROWS = K + 2;
    constexpr int XCOLS = K + 48;   // XCOLS-K = 48 (bank-offset 16: clean)
    const uint4* rt4 = (K == 17) ? d_rt17 : d_rt33;

    __shared__ unsigned xsT[XROWS * XCOLS];   // tf32 x tile

    int tid = threadIdx.x;
    int lane = tid & 31, wid = tid >> 5;
    int gid = lane >> 2, tig = lane & 3;
    int wm4 = wid >> 1;    // o tile: [32*wm4, 32*wm4+32)
    int wn = wid & 1;      // y row: y0 + wn
    int y0 = blockIdx.x * 2;
    int b = blockIdx.y >> 3, r = blockIdx.y & 7;

    // stage x tile as tf32 (zero-padded boundaries; extra tail row)
    const float* xb = x + b * NX * NX;
    for (int idx = tid; idx < XROWS * XCOLS; idx += 256) {
        int row = idx / XCOLS, col = idx - row * XCOLS;
        int gr = y0 + row - PAD, gc = col - PAD;
        float v = (gr >= 0 && gr < NX && gc >= 0 && gc < NX)
                      ? xb[gr * NX + gc] : 0.0f;
        xsT[idx] = f2tf(v);
    }
    __syncthreads();

    float acc[2][6][4];
#pragma unroll
    for (int m = 0; m < 2; ++m)
#pragma unroll
        for (int j = 0; j < 6; ++j)
#pragma unroll
            for (int e = 0; e < 4; ++e) acc[m][j][e] = 0.0f;

    const uint4* ap0 =
        rt4 + ((size_t)(r * 8 + 2 * wm4) * NCHK) * 32 + lane;
    const uint4* ap1 = ap0 + (size_t)NCHK * 32;

    // per-lane im2col trackers: k0 = 8*kc + tig, k1 = k0 + 4
    int row0 = 0, col0 = tig;
    int row1 = 0, col1 = tig + 4;

    uint4 c0 = ap0[0], c1 = ap1[0];

#pragma unroll 1
    for (int kc = 0; kc < NCHK; ++kc) {
        int nx = (kc + 1 < NCHK) ? kc + 1 : kc;
        uint4 n0 = ap0[(size_t)nx * 32];
        uint4 n1 = ap1[(size_t)nx * 32];

        const unsigned* b0p = xsT + (wn + row0) * XCOLS + gid + col0;
        const unsigned* b1p = xsT + (wn + row1) * XCOLS + gid + col1;
#pragma unroll
        for (int j = 0; j < 6; ++j) {
            unsigned bb0 = b0p[j * 8];
            unsigned bb1 = b1p[j * 8];
            MMA_TF32(acc[0][j], c0.x, c0.y, c0.z, c0.w, bb0, bb1);
            MMA_TF32(acc[1][j], c1.x, c1.y, c1.z, c1.w, bb0, bb1);
        }
        c0 = n0;
        c1 = n1;
        col0 += 8; if (col0 >= K) { col0 -= K; ++row0; }
        col1 += 8; if (col1 >= K) { col1 -= K; ++row1; }
    }

    // gumbel-softmax alpha over kernel sizes
    float l0 = (kw[0] + gk[0]) / 10.0f;
    float l1 = (kw[1] + gk[1]) / 10.0f;
    float mm = fmaxf(l0, l1);
    float e0 = expf(l0 - mm), e1 = expf(l1 - mm);
    float alpha = (FIRST ? e0 : e1) / (e0 + e1);

    int y = y0 + wn;
#pragma unroll
    for (int m = 0; m < 2; ++m) {
        int o_lo = 32 * wm4 + 16 * m + gid;
        int o_hi = o_lo + 8;
        float blo = bias[o_lo], bhi = bias[o_hi];
#pragma unroll
        for (int j = 0; j < 6; ++j) {
            int xc = j * 8 + 2 * tig;
#pragma unroll
            for (int half = 0; half < 2; ++half) {
                int o = half ? o_hi : o_lo;
                float bb = half ? bhi : blo;
                float v0 = acc[m][j][2 * half + 0] + bb;
                float v1 = acc[m][j][2 * half + 1] + bb;
                v0 = (v0 >= 0.0f) ? v0 : 0.01f * v0;
                v1 = (v1 >= 0.0f) ? v1 : 0.01f * v1;
                v0 *= alpha;
                v1 *= alpha;
                float2* p = (float2*)(d_xout
                                      + (((b * NO + o) * NR + r) * NHW)
                                      + y * 48 + xc);
                if (FIRST) {
                    *p = make_float2(v0, v1);
                } else {
                    float2 old = *p;
                    *p = make_float2(old.x + v0, old.y + v1);
                }
            }
        }
    }
}

// ============================================================
// K3: fused conv2 + lrelu + conva/convz heads via tf32 mma
//   block: one (b, r), M=128 o x N=48, 256 thr
//   8 warps: wm4 = wid>>1 (32 o), wn = wid&1 (24 n each)
//   16 k-chunks (C=128 exact). Heads reduced via shfl over the
//   o-lanes then cross-warp smem sum.
// ============================================================
template <int BRANCH>
__global__ __launch_bounds__(256, 3) void gemm_mma(
    const float* __restrict__ b2, const float* __restrict__ wa,
    const float* __restrict__ ba, const float* __restrict__ wz,
    const float* __restrict__ bz) {
    constexpr int RCOUNT = BRANCH ? 8 : 4;
    constexpr int RSTEP = BRANCH ? 1 : 2;
    float* attn_out = BRANCH ? d_attn1 : d_attn0;
    float* z_out = BRANCH ? d_z1 : d_z0;

    __shared__ unsigned xt[128 * 56];      // tf32 X tile [c][n], stride 56
    __shared__ float hbuf[4][5][48];       // per-wm4 head partials

    int tid = threadIdx.x;
    int lane = tid & 31, wid = tid >> 5;
    int gid = lane >> 2, tig = lane & 3;
    int wm4 = wid >> 1;
    int wn = wid & 1;
    int n0 = blockIdx.x * 48;
    int brs = blockIdx.y;
    int b = brs / RCOUNT;
    int rsub = brs - b * RCOUNT;
    int r = rsub * RSTEP;

    const float* xb = d_xout + ((b * NO) * NR + r) * NHW + n0;
    for (int idx = tid; idx < 128 * 48; idx += 256) {
        int c = idx / 48, n = idx - c * 48;
        xt[c * 56 + n] = f2tf(xb[c * (NR * NHW) + n]);
    }
    __syncthreads();

    float acc[2][3][4];
#pragma unroll
    for (int m = 0; m < 2; ++m)
#pragma unroll
        for (int j = 0; j < 3; ++j)
#pragma unroll
            for (int e = 0; e < 4; ++e) acc[m][j][e] = 0.0f;

    const uint4* ap = d_w2f + ((BRANCH * 8 + 2 * wm4) * 16) * 32 + lane;
#pragma unroll
    for (int kc = 0; kc < 16; ++kc) {
        uint4 A0 = ap[kc * 32];
        uint4 A1 = ap[512 + kc * 32];   // wset+1 (16*32)
        const unsigned* bp = xt + (kc * 8 + tig) * 56 + wn * 24 + gid;
#pragma unroll
        for (int j = 0; j < 3; ++j) {
            unsigned b0 = bp[j * 8];
            unsigned b1 = bp[j * 8 + 4 * 56];
            MMA_TF32(acc[0][j], A0.x, A0.y, A0.z, A0.w, b0, b1);
            MMA_TF32(acc[1][j], A1.x, A1.y, A1.z, A1.w, b0, b1);
        }
    }

    // epilogue: h = lrelu(acc + b2[o]); head partials per lane
    float pa[3][2];
    float pz[4][3][2];
#pragma unroll
    for (int j = 0; j < 3; ++j)
#pragma unroll
        for (int c01 = 0; c01 < 2; ++c01) {
            pa[j][c01] = 0.0f;
#pragma unroll
            for (int l = 0; l < 4; ++l) pz[l][j][c01] = 0.0f;
        }

#pragma unroll
    for (int m = 0; m < 2; ++m) {
#pragma unroll
        for (int eh = 0; eh < 2; ++eh) {
            int o = 32 * wm4 + 16 * m + 8 * eh + gid;
            float bb = b2[o];
            float wav = wa[o];
            float w0 = wz[o], w1 = wz[128 + o], w2v = wz[256 + o],
                  w3 = wz[384 + o];
#pragma unroll
            for (int j = 0; j < 3; ++j) {
#pragma unroll
                for (int c01 = 0; c01 < 2; ++c01) {
                    float hv = acc[m][j][2 * eh + c01] + bb;
                    hv = (hv >= 0.0f) ? hv : 0.01f * hv;
                    pa[j][c01] = fmaf(wav, hv, pa[j][c01]);
                    pz[0][j][c01] = fmaf(w0, hv, pz[0][j][c01]);
                    pz[1][j][c01] = fmaf(w1, hv, pz[1][j][c01]);
                    pz[2][j][c01] = fmaf(w2v, hv, pz[2][j][c01]);
                    pz[3][j][c01] = fmaf(w3, hv, pz[3][j][c01]);
                }
            }
        }
    }

    // reduce over the 8 o-lane groups (lane bits 2..4)
#pragma unroll
    for (int msk = 4; msk <= 16; msk <<= 1) {
#pragma unroll
        for (int j = 0; j < 3; ++j)
#pragma unroll
            for (int c01 = 0; c01 < 2; ++c01) {
                pa[j][c01] += __shfl_xor_sync(0xffffffffu, pa[j][c01], msk);
#pragma unroll
                for (int l = 0; l < 4; ++l)
                    pz[l][j][c01] +=
                        __shfl_xor_sync(0xffffffffu, pz[l][j][c01], msk);
            }
    }

    if (lane < 4) {  // lane == tig; all gid-groups hold identical sums
#pragma unroll
        for (int j = 0; j < 3; ++j)
#pragma unroll
            for (int c01 = 0; c01 < 2; ++c01) {
                int nl = wn * 24 + j * 8 + 2 * lane + c01;
                hbuf[wm4][0][nl] = pa[j][c01];
#pragma unroll
                for (int l = 0; l < 4; ++l)
                    hbuf[wm4][1 + l][nl] = pz[l][j][c01];
            }
    }
    __syncthreads();

    for (int idx = tid; idx < 5 * 48; idx += 256) {
        int h = idx / 48, nl = idx - h * 48;
        float s = hbuf[0][h][nl] + hbuf[1][h][nl] + hbuf[2][h][nl]
                + hbuf[3][h][nl];
        int ng = n0 + nl;
        if (h == 0)
            attn_out[(b * RCOUNT + rsub) * NHW + ng] = s + ba[0];
        else
            z_out[((b * 4 + (h - 1)) * RCOUNT + rsub) * NHW + ng] =
                s + bz[h - 1];
    }
}

// ============================================================
// K4: scatter combine (betas) + p_r; writes attn, z, theta,
//     p_r, offsets directly into d_out
// ============================================================
__global__ void combine_kern(const float* __restrict__ rw,
                             const float* __restrict__ gr,
                             float* __restrict__ out) {
    int idx = blockIdx.x * blockDim.x + threadIdx.x;
    if (idx >= NB * NR * NHW) return;

    float l0 = (rw[0] + gr[0]) / 10.0f;
    float l1 = (rw[1] + gr[1]) / 10.0f;
    float mm = fmaxf(l0, l1);
    float e0 = expf(l0 - mm), e1 = expf(l1 - mm);
    float inv = 1.0f / (e0 + e1);
    float b0 = e0 * inv, b1 = e1 * inv;

    int b = idx / (NR * NHW);
    int rem = idx - b * (NR * NHW);
    int r = rem / NHW;
    int hw = rem - r * NHW;
    float off = c_offs[r];
    float t = off / PI_F;
    float pr = -0.5f * t * t - LOG_SIGMA - HALF_LOG2PI;

    float a = b1 * d_attn1[(b * NR + r) * NHW + hw];
    bool even = ((r & 1) == 0);
    if (even) a += b0 * d_attn0[(b * 4 + (r >> 1)) * NHW + hw];
    a += pr;
    out[OFF_ATTN + idx] = a;

    float zv[4];
#pragma unroll
    for (int l = 0; l < 4; ++l) {
        float z = b1 * d_z1[((b * 4 + l) * NR + r) * NHW + hw];
        if (even) z += b0 * d_z0[((b * 4 + l) * 4 + (r >> 1)) * NHW + hw];
        zv[l] = z;
        out[OFF_Z + ((b * 4 + l) * NR + r) * NHW + hw] = z;
    }
    out[OFF_TH + ((b * 2 + 0) * NR + r) * NHW + hw] = zv[0] + off;
    out[OFF_TH + ((b * 2 + 1) * NR + r) * NHW + hw] = zv[1];

    if (idx < 8) {
        float o2 = c_offs[idx];
        float t2 = o2 / PI_F;
        out[OFF_PR + idx] = -0.5f * t2 * t2 - LOG_SIGMA - HALF_LOG2PI;
        out[OFF_OFF + idx] = o2;
    }
}

// ============================================================
// K5: per-batch softmax stats (max / sumexp, two distributions)
// ============================================================
__global__ void stats_kern(const float* __restrict__ out,
                           const float* __restrict__ g) {
    __shared__ float sm[256];
    int b = blockIdx.x, tid = threadIdx.x;
    const float* a = out + OFF_ATTN + b * (NR * NHW);
    const float* gb = g + b * (NR * NHW);

    float m1 = -1e30f, m2 = -1e30f;
    for (int i = tid; i < NR * NHW; i += 256) {
        float v = a[i];
        m1 = fmaxf(m1, v);
        m2 = fmaxf(m2, v + gb[i]);
    }
    sm[tid] = m1; __syncthreads();
    for (int s = 128; s > 0; s >>= 1) {
        if (tid < s) sm[tid] = fmaxf(sm[tid], sm[tid + s]);
        __syncthreads();
    }
    m1 = sm[0]; __syncthreads();
    sm[tid] = m2; __syncthreads();
    for (int s = 128; s > 0; s >>= 1) {
        if (tid < s) sm[tid] = fmaxf(sm[tid], sm[tid + s]);
        __syncthreads();
    }
    m2 = sm[0]; __syncthreads();

    float s1 = 0.0f, s2 = 0.0f;
    for (int i = tid; i < NR * NHW; i += 256) {
        float v = a[i];
        s1 += expf(v - m1);
        s2 += expf(v + gb[i] - m2);
    }
    sm[tid] = s1; __syncthreads();
    for (int s = 128; s > 0; s >>= 1) {
        if (tid < s) sm[tid] += sm[tid + s];
        __syncthreads();
    }
    s1 = sm[0]; __syncthreads();
    sm[tid] = s2; __syncthreads();
    for (int s = 128; s > 0; s >>= 1) {
        if (tid < s) sm[tid] += sm[tid + s];
        __syncthreads();
    }
    s2 = sm[0];

    if (tid == 0) {
        d_stats[b * 4 + 0] = m1;
        d_stats[b * 4 + 1] = s1;
        d_stats[b * 4 + 2] = m2;
        d_stats[b * 4 + 3] = s2;
    }
}

// ============================================================
// K6: q_t_r (log_softmax) + a_sampled (gumbel softmax)
// ============================================================
__global__ void final_kern(const float* __restrict__ g,
                           float* __restrict__ out) {
    int idx = blockIdx.x * blockDim.x + threadIdx.x;
    if (idx >= NB * NR * NHW) return;
    int b = idx / (NR * NHW);
    float v = out[OFF_ATTN + idx];
    out[OFF_Q + idx] = (v - d_stats[b * 4 + 0]) - logf(d_stats[b * 4 + 1]);
    out[OFF_A + idx] =
        expf(v + g[idx] - d_stats[b * 4 + 2]) / d_stats[b * 4 + 3];
}

// ============================================================
extern "C" void kernel_launch(void* const* d_in, const int* in_sizes, int n_in,
                              void* d_out, int out_size) {
    const float* x   = (const float*)d_in[0];
    const float* ksw = (const float*)d_in[1];
    const float* rdw = (const float*)d_in[2];
    const float* w17 = (const float*)d_in[3];
    const float* b17 = (const float*)d_in[4];
    const float* w33 = (const float*)d_in[5];
    const float* b33 = (const float*)d_in[6];
    const float* w2  = (const float*)d_in[7];
    const float* b2  = (const float*)d_in[8];
    const float* wa  = (const float*)d_in[9];
    const float* ba  = (const float*)d_in[10];
    const float* wz  = (const float*)d_in[11];
    const float* bz  = (const float*)d_in[12];
    const float* gk  = (const float*)d_in[13];
    const float* gr  = (const float*)d_in[14];
    const float* ga  = (const float*)d_in[15];
    float* out = (float*)d_out;

    // word counts: K=17: 8*8*37*128 = 303104; K=33: 8*8*137*128 = 1122304
    rotate_tf<17, 37><<<(303104 + 255) / 256, 256>>>(w17);
    rotate_tf<33, 137><<<(1122304 + 255) / 256, 256>>>(w33);
    w2_frag<<<(32768 + 255) / 256, 256>>>(w2);

    conv_mma<17, 0, 37, true  ><<<dim3(24, 64), 256>>>(x, b17, ksw, gk);
    conv_mma<33, 8, 137, false><<<dim3(24, 64), 256>>>(x, b33, ksw, gk);

    gemm_mma<1><<<dim3(48, 64), 256>>>(b2 + 128, wa + 128, ba + 1,
                                       wz + 512, bz + 4);
    gemm_mma<0><<<dim3(48, 32), 256>>>(b2, wa, ba, wz, bz);

    combine_kern<<<(NB * NR * NHW + 255) / 256, 256>>>(rdw, gr, out);
    stats_kern<<<NB, 256>>>(out, ga);
    final_kern<<<(NB * NR * NHW + 255) / 256, 256>>>(ga, out);
}

// round 10
// speedup vs baseline: 4.9905x; 1.3819x over previous
#include <cuda_runtime.h>
#include <cuda_fp16.h>
#include <math.h>

#define NB 8
#define NO 128
#define NR 8
#define NH 48
#define NHW 2304
#define NX 64

// ---- output layout (concatenated flattened outputs, float32) ----
#define OFF_ATTN 0
#define OFF_Q    147456
#define OFF_PR   294912
#define OFF_A    294920
#define OFF_OFF  442376
#define OFF_TH   442384
#define OFF_Z    737296

// ---- device scratch (static, no runtime allocation) ----
// fp16 conv weights in m16n8k16 A-fragment order over row-pairs:
//   pair p: row = p / PPR, col = 2*(p % PPR) (2nd elem zero if col+1 >= K)
//   [r][wset(8)][kc][lane(32)] -> uint4 (a0,a1,a2,a3), each = half2
//   K=17: PPR=9,  NCHK=20;  K=33: PPR=17, NCHK=71
__device__ uint4 d_rh17[NR * 8 * 20 * 32];
__device__ uint4 d_rh33[NR * 8 * 71 * 32];
// fp16 conv2 weights: [branch][wset(8)][kc(8)][lane(32)] -> uint4
__device__ uint4 d_w2h[2 * 8 * 8 * 32];
__device__ float d_xout[NB * NO * NR * NHW];     // [b][c][r][hw]
__device__ float d_attn1[NB * NR * NHW];
__device__ float d_attn0[NB * 4 * NHW];
__device__ float d_z1[NB * 4 * NR * NHW];        // [b][l][r][hw]
__device__ float d_z0[NB * 4 * 4 * NHW];
__device__ float d_stats[NB * 4];                // m1, s1, m2, s2

__constant__ float c_offs[8] = {
    0.0f, 0.7853981633974483f, 1.5707963267948966f, 2.356194490192345f,
    3.141592653589793f, -2.356194490192345f, -1.5707963267948966f,
    -0.7853981633974483f};

#define LOG_SIGMA   1.1447298858494002f   // log(pi), f32
#define HALF_LOG2PI 0.9189385332046727f   // 0.5*log(2*pi), f32
#define PI_F        3.14159265358979323846f

__device__ __forceinline__ unsigned packh2(float a, float b) {
    __half2 h = __floats2half2_rn(a, b);
    return *reinterpret_cast<unsigned*>(&h);
}

#define MMA_F16(c, a0, a1, a2, a3, b0, b1)                                  \
    asm volatile(                                                           \
        "mma.sync.aligned.m16n8k16.row.col.f32.f16.f16.f32 "                \
        "{%0,%1,%2,%3}, {%4,%5,%6,%7}, {%8,%9}, {%0,%1,%2,%3};"             \
        : "+f"((c)[0]), "+f"((c)[1]), "+f"((c)[2]), "+f"((c)[3])            \
        : "r"(a0), "r"(a1), "r"(a2), "r"(a3), "r"(b0), "r"(b1))

// bilinear grid_sample (zero pad) of rotated kernel, element (i,j), chan o
template <int K>
__device__ __forceinline__ float rot_sample(const float* __restrict__ w,
                                            int r, int o, int i, int j) {
    constexpr int KK = K * K;
    float theta = 0.7853981633974483f * (float)r;
    float c, s;
    __sincosf(theta, &s, &c);
    // use precise versions to match reference numerics
    c = cosf(theta); s = sinf(theta);
    float gy = (2.0f * (float)i + 1.0f) / (float)K - 1.0f;
    float gx = (2.0f * (float)j + 1.0f) / (float)K - 1.0f;
    float sx = c * gx - s * gy;
    float sy = s * gx + c * gy;
    float fx = ((sx + 1.0f) * (float)K - 1.0f) * 0.5f;
    float fy = ((sy + 1.0f) * (float)K - 1.0f) * 0.5f;
    int x0 = (int)floorf(fx);
    int y0 = (int)floorf(fy);
    float wx1 = fx - (float)x0;
    float wy1 = fy - (float)y0;
    const float* wo = w + o * KK;
    auto g = [&](int y, int x) -> float {
        if (y < 0 || y >= K || x < 0 || x >= K) return 0.0f;
        return wo[y * K + x];
    };
    return g(y0, x0) * (1.0f - wy1) * (1.0f - wx1)
         + g(y0, x0 + 1) * (1.0f - wy1) * wx1
         + g(y0 + 1, x0) * wy1 * (1.0f - wx1)
         + g(y0 + 1, x0 + 1) * wy1 * wx1;
}

// ============================================================
// K1: rotate -> fp16 pair-fragment layout
//   word idx = (((r*8+wset)*NCHK+kc)*32+lane)*4+q
//   o    = 16*wset + (lane>>2) + 8*(q&1)
//   pair = kc*8 + (lane&3) + 4*(q>>1) -> (row, col=2*pc), elems col, col+1
// ============================================================
template <int K, int PPR, int NCHK>
__global__ void rotate_h(const float* __restrict__ w) {
    unsigned* out = (K == 17) ? (unsigned*)d_rh17 : (unsigned*)d_rh33;
    int idx = blockIdx.x * blockDim.x + threadIdx.x;
    if (idx >= NR * 8 * NCHK * 128) return;

    int q = idx & 3;
    int lane = (idx >> 2) & 31;
    int t = idx >> 7;
    int kc = t % NCHK; t /= NCHK;
    int wset = t & 7;
    int r = t >> 3;

    int o = 16 * wset + (lane >> 2) + 8 * (q & 1);
    int p = kc * 8 + (lane & 3) + 4 * (q >> 1);
    int row = p / PPR;
    int col = 2 * (p - row * PPR);

    float w0 = 0.0f, w1 = 0.0f;
    if (row < K) {
        w0 = rot_sample<K>(w, r, o, row, col);
        if (col + 1 < K) w1 = rot_sample<K>(w, r, o, row, col + 1);
    }
    out[idx] = packh2(w0, w1);
}

// ============================================================
// K1b: conv2 weights -> fp16 fragment order
//   o = 16*wset + (lane>>2) + 8*(q&1); c = 16*kc + 2*(lane&3) + 8*(q>>1)
// ============================================================
__global__ void w2h_frag(const float* __restrict__ w2) {
    unsigned* out = (unsigned*)d_w2h;
    int idx = blockIdx.x * blockDim.x + threadIdx.x;
    if (idx >= 2 * 8 * 8 * 128) return;
    int q = idx & 3;
    int lane = (idx >> 2) & 31;
    int t = idx >> 7;
    int kc = t % 8; t /= 8;
    int wset = t & 7;
    int br = t >> 3;
    int o = 16 * wset + (lane >> 2) + 8 * (q & 1);
    int c = 16 * kc + 2 * (lane & 3) + 8 * (q >> 1);
    const float* wb = w2 + br * 16384 + o * 128;
    out[idx] = packh2(wb[c], wb[c + 1]);
}

// ============================================================
// K2: group conv via fp16 mma.sync m16n8k16 implicit-GEMM
//   block: one (b, r), M=128 o x N=96 (2 rows x 48), 256 thr
//   x tile staged TWICE in fp16 (even + shifted-by-one copies) so
//   every k-pair load is one aligned LDS.32; lane's copy fixed by
//   gid parity. Per-lane (row,pc) trackers; dist-1 A prefetch.
// ============================================================
template <int K, int PAD, int PPR, int NCHK, bool FIRST>
__global__ __launch_bounds__(256, 3) void conv_mma(
    const float* __restrict__ x, const float* __restrict__ bias,
    const float* __restrict__ kw, const float* __restrict__ gk) {
    constexpr int XCOLS = K + 49;        // fp16 columns (even)
    constexpr int XC2 = XCOLS / 2;       // 32-bit words per row
    constexpr int XROWS = K + 2;
    const uint4* rt4 = (K == 17) ? d_rh17 : d_rh33;

    __shared__ unsigned xsE[XROWS * XC2];
    __shared__ unsigned xsO[XROWS * XC2];

    int tid = threadIdx.x;
    int lane = tid & 31, wid = tid >> 5;
    int gid = lane >> 2, tig = lane & 3;
    int wm4 = wid >> 1;    // o tile: [32*wm4, 32*wm4+32)
    int wn = wid & 1;      // y row: y0 + wn
    int y0 = blockIdx.x * 2;
    int b = blockIdx.y >> 3, r = blockIdx.y & 7;

    const float* xb = x + b * NX * NX;
    for (int idx = tid; idx < XROWS * XC2; idx += 256) {
        int row = idx / XC2, cw = idx - row * XC2;
        int gr = y0 + row - PAD;
        float v0 = 0.0f, v1 = 0.0f, v2 = 0.0f;
        if (gr >= 0 && gr < NX) {
            int gc = 2 * cw - PAD;
            if (gc >= 0 && gc < NX) v0 = xb[gr * NX + gc];
            if (gc + 1 >= 0 && gc + 1 < NX) v1 = xb[gr * NX + gc + 1];
            if (gc + 2 >= 0 && gc + 2 < NX) v2 = xb[gr * NX + gc + 2];
        }
        xsE[idx] = packh2(v0, v1);
        xsO[idx] = packh2(v1, v2);
    }
    __syncthreads();

    float acc[2][6][4];
#pragma unroll
    for (int m = 0; m < 2; ++m)
#pragma unroll
        for (int j = 0; j < 6; ++j)
#pragma unroll
            for (int e = 0; e < 4; ++e) acc[m][j][e] = 0.0f;

    const uint4* ap0 =
        rt4 + ((size_t)(r * 8 + 2 * wm4) * NCHK) * 32 + lane;
    const uint4* ap1 = ap0 + (size_t)NCHK * 32;

    // per-lane pair trackers: b0 pair = 8*kc + tig; b1 pair = +4
    int row0 = 0, pc0 = tig;
    int row1 = 0, pc1 = tig + 4;
    const unsigned* cb = (gid & 1) ? xsO : xsE;
    int g2 = gid >> 1;

    uint4 c0 = ap0[0], c1 = ap1[0];

#pragma unroll 1
    for (int kc = 0; kc < NCHK; ++kc) {
        int nx = (kc + 1 < NCHK) ? kc + 1 : kc;
        uint4 n0 = ap0[(size_t)nx * 32];
        uint4 n1 = ap1[(size_t)nx * 32];

        const unsigned* b0p = cb + (wn + row0) * XC2 + pc0 + g2;
        const unsigned* b1p = cb + (wn + row1) * XC2 + pc1 + g2;
#pragma unroll
        for (int j = 0; j < 6; ++j) {
            unsigned bb0 = b0p[j * 4];
            unsigned bb1 = b1p[j * 4];
            MMA_F16(acc[0][j], c0.x, c0.y, c0.z, c0.w, bb0, bb1);
            MMA_F16(acc[1][j], c1.x, c1.y, c1.z, c1.w, bb0, bb1);
        }
        c0 = n0;
        c1 = n1;
        pc0 += 8; if (pc0 >= PPR) { pc0 -= PPR; ++row0; }
        pc1 += 8; if (pc1 >= PPR) { pc1 -= PPR; ++row1; }
    }

    // gumbel-softmax alpha over kernel sizes
    float l0 = (kw[0] + gk[0]) / 10.0f;
    float l1 = (kw[1] + gk[1]) / 10.0f;
    float mm = fmaxf(l0, l1);
    float e0 = expf(l0 - mm), e1 = expf(l1 - mm);
    float alpha = (FIRST ? e0 : e1) / (e0 + e1);

    int y = y0 + wn;
#pragma unroll
    for (int m = 0; m < 2; ++m) {
        int o_lo = 32 * wm4 + 16 * m + gid;
        int o_hi = o_lo + 8;
        float blo = bias[o_lo], bhi = bias[o_hi];
#pragma unroll
        for (int j = 0; j < 6; ++j) {
            int xc = j * 8 + 2 * tig;
#pragma unroll
            for (int half = 0; half < 2; ++half) {
                int o = half ? o_hi : o_lo;
                float bb = half ? bhi : blo;
                float v0 = acc[m][j][2 * half + 0] + bb;
                float v1 = acc[m][j][2 * half + 1] + bb;
                v0 = (v0 >= 0.0f) ? v0 : 0.01f * v0;
                v1 = (v1 >= 0.0f) ? v1 : 0.01f * v1;
                v0 *= alpha;
                v1 *= alpha;
                float2* p = (float2*)(d_xout
                                      + (((b * NO + o) * NR + r) * NHW)
                                      + y * 48 + xc);
                if (FIRST) {
                    *p = make_float2(v0, v1);
                } else {
                    float2 old = *p;
                    *p = make_float2(old.x + v0, old.y + v1);
                }
            }
        }
    }
}

// ============================================================
// K3: fused conv2 + lrelu + conva/convz heads via fp16 mma
//   block: one (b, r), M=128 o x N=48, 256 thr; 8 k-chunks
//   x tile staged transposed [n][c] fp16 (stride 68 words) so B
//   pairs (c, c+1) are single aligned LDS.32, conflict-free.
// ============================================================
template <int BRANCH>
__global__ __launch_bounds__(256, 3) void gemm_mma(
    const float* __restrict__ b2, const float* __restrict__ wa,
    const float* __restrict__ ba, const float* __restrict__ wz,
    const float* __restrict__ bz) {
    constexpr int RCOUNT = BRANCH ? 8 : 4;
    constexpr int RSTEP = BRANCH ? 1 : 2;
    constexpr int STW = 68;   // words per n-row (64 + 4 pad)
    float* attn_out = BRANCH ? d_attn1 : d_attn0;
    float* z_out = BRANCH ? d_z1 : d_z0;

    __shared__ unsigned xtw[48 * STW];     // [n][c/2] fp16 pairs
    __shared__ float hbuf[4][5][48];       // per-wm4 head partials

    int tid = threadIdx.x;
    int lane = tid & 31, wid = tid >> 5;
    int gid = lane >> 2, tig = lane & 3;
    int wm4 = wid >> 1;
    int wn = wid & 1;
    int n0 = blockIdx.x * 48;
    int brs = blockIdx.y;
    int b = brs / RCOUNT;
    int rsub = brs - b * RCOUNT;
    int r = rsub * RSTEP;

    const float* xb = d_xout + ((b * NO) * NR + r) * NHW + n0;
    const int S = NR * NHW;
    for (int idx = tid; idx < 48 * 64; idx += 256) {
        int cw = idx / 48, n = idx - cw * 48;
        float v0 = xb[(2 * cw) * S + n];
        float v1 = xb[(2 * cw + 1) * S + n];
        xtw[n * STW + cw] = packh2(v0, v1);
    }
    __syncthreads();

    float acc[2][3][4];
#pragma unroll
    for (int m = 0; m < 2; ++m)
#pragma unroll
        for (int j = 0; j < 3; ++j)
#pragma unroll
            for (int e = 0; e < 4; ++e) acc[m][j][e] = 0.0f;

    const uint4* ap = d_w2h + ((BRANCH * 8 + 2 * wm4) * 8) * 32 + lane;
    const unsigned* bp = xtw + (wn * 24 + gid) * STW + tig;
#pragma unroll
    for (int kc = 0; kc < 8; ++kc) {
        uint4 A0 = ap[kc * 32];
        uint4 A1 = ap[256 + kc * 32];   // next wset (8*32)
#pragma unroll
        for (int j = 0; j < 3; ++j) {
            unsigned b0 = bp[j * 8 * STW + 8 * kc];
            unsigned b1 = bp[j * 8 * STW + 8 * kc + 4];
            MMA_F16(acc[0][j], A0.x, A0.y, A0.z, A0.w, b0, b1);
            MMA_F16(acc[1][j], A1.x, A1.y, A1.z, A1.w, b0, b1);
        }
    }

    // epilogue: h = lrelu(acc + b2[o]); head partials per lane
    float pa[3][2];
    float pz[4][3][2];
#pragma unroll
    for (int j = 0; j < 3; ++j)
#pragma unroll
        for (int c01 = 0; c01 < 2; ++c01) {
            pa[j][c01] = 0.0f;
#pragma unroll
            for (int l = 0; l < 4; ++l) pz[l][j][c01] = 0.0f;
        }

#pragma unroll
    for (int m = 0; m < 2; ++m) {
#pragma unroll
        for (int eh = 0; eh < 2; ++eh) {
            int o = 32 * wm4 + 16 * m + 8 * eh + gid;
            float bb = b2[o];
            float wav = wa[o];
            float w0 = wz[o], w1 = wz[128 + o], w2v = wz[256 + o],
                  w3 = wz[384 + o];
#pragma unroll
            for (int j = 0; j < 3; ++j) {
#pragma unroll
                for (int c01 = 0; c01 < 2; ++c01) {
                    float hv = acc[m][j][2 * eh + c01] + bb;
                    hv = (hv >= 0.0f) ? hv : 0.01f * hv;
                    pa[j][c01] = fmaf(wav, hv, pa[j][c01]);
                    pz[0][j][c01] = fmaf(w0, hv, pz[0][j][c01]);
                    pz[1][j][c01] = fmaf(w1, hv, pz[1][j][c01]);
                    pz[2][j][c01] = fmaf(w2v, hv, pz[2][j][c01]);
                    pz[3][j][c01] = fmaf(w3, hv, pz[3][j][c01]);
                }
            }
        }
    }

    // reduce over the 8 o-lane groups (lane bits 2..4)
#pragma unroll
    for (int msk = 4; msk <= 16; msk <<= 1) {
#pragma unroll
        for (int j = 0; j < 3; ++j)
#pragma unroll
            for (int c01 = 0; c01 < 2; ++c01) {
                pa[j][c01] += __shfl_xor_sync(0xffffffffu, pa[j][c01], msk);
#pragma unroll
                for (int l = 0; l < 4; ++l)
                    pz[l][j][c01] +=
                        __shfl_xor_sync(0xffffffffu, pz[l][j][c01], msk);
            }
    }

    if (lane < 4) {  // lane == tig; all gid-groups hold identical sums
#pragma unroll
        for (int j = 0; j < 3; ++j)
#pragma unroll
            for (int c01 = 0; c01 < 2; ++c01) {
                int nl = wn * 24 + j * 8 + 2 * lane + c01;
                hbuf[wm4][0][nl] = pa[j][c01];
#pragma unroll
                for (int l = 0; l < 4; ++l)
                    hbuf[wm4][1 + l][nl] = pz[l][j][c01];
            }
    }
    __syncthreads();

    for (int idx = tid; idx < 5 * 48; idx += 256) {
        int h = idx / 48, nl = idx - h * 48;
        float s = hbuf[0][h][nl] + hbuf[1][h][nl] + hbuf[2][h][nl]
                + hbuf[3][h][nl];
        int ng = n0 + nl;
        if (h == 0)
            attn_out[(b * RCOUNT + rsub) * NHW + ng] = s + ba[0];
        else
            z_out[((b * 4 + (h - 1)) * RCOUNT + rsub) * NHW + ng] =
                s + bz[h - 1];
    }
}

// ============================================================
// K4: scatter combine (betas) + p_r; writes attn, z, theta,
//     p_r, offsets directly into d_out
// ============================================================
__global__ void combine_kern(const float* __restrict__ rw,
                             const float* __restrict__ gr,
                             float* __restrict__ out) {
    int idx = blockIdx.x * blockDim.x + threadIdx.x;
    if (idx >= NB * NR * NHW) return;

    float l0 = (rw[0] + gr[0]) / 10.0f;
    float l1 = (rw[1] + gr[1]) / 10.0f;
    float mm = fmaxf(l0, l1);
    float e0 = expf(l0 - mm), e1 = expf(l1 - mm);
    float inv = 1.0f / (e0 + e1);
    float b0 = e0 * inv, b1 = e1 * inv;

    int b = idx / (NR * NHW);
    int rem = idx - b * (NR * NHW);
    int r = rem / NHW;
    int hw = rem - r * NHW;
    float off = c_offs[r];
    float t = off / PI_F;
    float pr = -0.5f * t * t - LOG_SIGMA - HALF_LOG2PI;

    float a = b1 * d_attn1[(b * NR + r) * NHW + hw];
    bool even = ((r & 1) == 0);
    if (even) a += b0 * d_attn0[(b * 4 + (r >> 1)) * NHW + hw];
    a += pr;
    out[OFF_ATTN + idx] = a;

    float zv[4];
#pragma unroll
    for (int l = 0; l < 4; ++l) {
        float z = b1 * d_z1[((b * 4 + l) * NR + r) * NHW + hw];
        if (even) z += b0 * d_z0[((b * 4 + l) * 4 + (r >> 1)) * NHW + hw];
        zv[l] = z;
        out[OFF_Z + ((b * 4 + l) * NR + r) * NHW + hw] = z;
    }
    out[OFF_TH + ((b * 2 + 0) * NR + r) * NHW + hw] = zv[0] + off;
    out[OFF_TH + ((b * 2 + 1) * NR + r) * NHW + hw] = zv[1];

    if (idx < 8) {
        float o2 = c_offs[idx];
        float t2 = o2 / PI_F;
        out[OFF_PR + idx] = -0.5f * t2 * t2 - LOG_SIGMA - HALF_LOG2PI;
        out[OFF_OFF + idx] = o2;
    }
}

// ============================================================
// K5: per-batch softmax stats (max / sumexp, two distributions)
// ============================================================
__global__ void stats_kern(const float* __restrict__ out,
                           const float* __restrict__ g) {
    __shared__ float sm[256];
    int b = blockIdx.x, tid = threadIdx.x;
    const float* a = out + OFF_ATTN + b * (NR * NHW);
    const float* gb = g + b * (NR * NHW);

    float m1 = -1e30f, m2 = -1e30f;
    for (int i = tid; i < NR * NHW; i += 256) {
        float v = a[i];
        m1 = fmaxf(m1, v);
        m2 = fmaxf(m2, v + gb[i]);
    }
    sm[tid] = m1; __syncthreads();
    for (int s = 128; s > 0; s >>= 1) {
        if (tid < s) sm[tid] = fmaxf(sm[tid], sm[tid + s]);
        __syncthreads();
    }
    m1 = sm[0]; __syncthreads();
    sm[tid] = m2; __syncthreads();
    for (int s = 128; s > 0; s >>= 1) {
        if (tid < s) sm[tid] = fmaxf(sm[tid], sm[tid + s]);
        __syncthreads();
    }
    m2 = sm[0]; __syncthreads();

    float s1 = 0.0f, s2 = 0.0f;
    for (int i = tid; i < NR * NHW; i += 256) {
        float v = a[i];
        s1 += expf(v - m1);
        s2 += expf(v + gb[i] - m2);
    }
    sm[tid] = s1; __syncthreads();
    for (int s = 128; s > 0; s >>= 1) {
        if (tid < s) sm[tid] += sm[tid + s];
        __syncthreads();
    }
    s1 = sm[0]; __syncthreads();
    sm[tid] = s2; __syncthreads();
    for (int s = 128; s > 0; s >>= 1) {
        if (tid < s) sm[tid] += sm[tid + s];
        __syncthreads();
    }
    s2 = sm[0];

    if (tid == 0) {
        d_stats[b * 4 + 0] = m1;
        d_stats[b * 4 + 1] = s1;
        d_stats[b * 4 + 2] = m2;
        d_stats[b * 4 + 3] = s2;
    }
}

// ============================================================
// K6: q_t_r (log_softmax) + a_sampled (gumbel softmax)
// ============================================================
__global__ void final_kern(const float* __restrict__ g,
                           float* __restrict__ out) {
    int idx = blockIdx.x * blockDim.x + threadIdx.x;
    if (idx >= NB * NR * NHW) return;
    int b = idx / (NR * NHW);
    float v = out[OFF_ATTN + idx];
    out[OFF_Q + idx] = (v - d_stats[b * 4 + 0]) - logf(d_stats[b * 4 + 1]);
    out[OFF_A + idx] =
        expf(v + g[idx] - d_stats[b * 4 + 2]) / d_stats[b * 4 + 3];
}

// ============================================================
extern "C" void kernel_launch(void* const* d_in, const int* in_sizes, int n_in,
                              void* d_out, int out_size) {
    const float* x   = (const float*)d_in[0];
    const float* ksw = (const float*)d_in[1];
    const float* rdw = (const float*)d_in[2];
    const float* w17 = (const float*)d_in[3];
    const float* b17 = (const float*)d_in[4];
    const float* w33 = (const float*)d_in[5];
    const float* b33 = (const float*)d_in[6];
    const float* w2  = (const float*)d_in[7];
    const float* b2  = (const float*)d_in[8];
    const float* wa  = (const float*)d_in[9];
    const float* ba  = (const float*)d_in[10];
    const float* wz  = (const float*)d_in[11];
    const float* bz  = (const float*)d_in[12];
    const float* gk  = (const float*)d_in[13];
    const float* gr  = (const float*)d_in[14];
    const float* ga  = (const float*)d_in[15];
    float* out = (float*)d_out;

    // word counts: K=17: 8*8*20*128 = 163840; K=33: 8*8*71*128 = 581632
    rotate_h<17, 9, 20><<<(163840 + 255) / 256, 256>>>(w17);
    rotate_h<33, 17, 71><<<(581632 + 255) / 256, 256>>>(w33);
    w2h_frag<<<(16384 + 255) / 256, 256>>>(w2);

    conv_mma<17, 0, 9, 20, true  ><<<dim3(24, 64), 256>>>(x, b17, ksw, gk);
    conv_mma<33, 8, 17, 71, false><<<dim3(24, 64), 256>>>(x, b33, ksw, gk);

    gemm_mma<1><<<dim3(48, 64), 256>>>(b2 + 128, wa + 128, ba + 1,
                                       wz + 512, bz + 4);
    gemm_mma<0><<<dim3(48, 32), 256>>>(b2, wa, ba, wz, bz);

    combine_kern<<<(NB * NR * NHW + 255) / 256, 256>>>(rdw, gr, out);
    stats_kern<<<NB, 256>>>(out, ga);
    final_kern<<<(NB * NR * NHW + 255) / 256, 256>>>(ga, out);
}